// round 9
// baseline (speedup 1.0000x reference)
#include <cuda_runtime.h>
#include <math.h>

// ---------------- problem constants ----------------
#define BN   4
#define TN   16000
#define NCN  80
#define NRN  64
#define NLN  16
#define TT   128     // t-tile for layer + gemm kernels

// ---------------- device scratch (static, no dynamic alloc) ----------------
__device__ float g_cond[BN * NCN * TN];            //  [b][c][t]   20.5 MB
__device__ float g_x0  [BN * NRN * TN];            //  [b][k][t]   16.4 MB
__device__ float g_x1  [BN * NRN * TN];
__device__ float g_acts[NLN * BN * NRN * TN];      //  [i][b][k][t] 262 MB
__device__ float g_h1  [BN * 256 * TN];            //  [b][o][t]   65.5 MB
__device__ float g_h2  [BN * 256 * TN];

typedef unsigned long long ull;

// ---------------- packed f32x2 helpers (sm_103a FFMA2) ----------------
__device__ __forceinline__ void ffma2(ull& d, ull a, ull b) {
    asm("fma.rn.f32x2 %0, %1, %2, %0;" : "+l"(d) : "l"(a), "l"(b));
}
__device__ __forceinline__ ull add2(ull a, ull b) {
    ull r; asm("add.rn.f32x2 %0, %1, %2;" : "=l"(r) : "l"(a), "l"(b)); return r;
}
__device__ __forceinline__ ull pk2(float x, float y) {
    ull r; asm("mov.b64 %0, {%1, %2};" : "=l"(r) : "f"(x), "f"(y)); return r;
}
__device__ __forceinline__ ull bcast2(float x) {
    ull r; asm("mov.b64 %0, {%1, %1};" : "=l"(r) : "f"(x)); return r;
}
__device__ __forceinline__ float2 up2(ull v) {
    float2 f; asm("mov.b64 {%0, %1}, %2;" : "=f"(f.x), "=f"(f.y) : "l"(v)); return f;
}

// ---------------- fast activations ----------------
__device__ __forceinline__ float fast_sigmoid(float x) {
    return __fdividef(1.0f, 1.0f + __expf(-x));
}
__device__ __forceinline__ float fast_tanh(float x) {
    float ax = fabsf(x);
    float e  = __expf(-2.0f * ax);
    float t  = __fdividef(1.0f - e, 1.0f + e);
    return copysignf(t, x);
}

// ===========================================================================
// Kernel 1: transposed-conv upsampler by output phase (640 thr, FFMA2).
// ===========================================================================
#define UPS_SMEM_FLOATS (25600 + 25600)
__global__ __launch_bounds__(640, 1)
void k_upsample(const float* __restrict__ features,
                const float* __restrict__ up_w,
                const float* __restrict__ up_b)
{
    extern __shared__ float sm[];
    float* ws = sm;            // [j][i][o] : 4*80*80
    float* fs = sm + 25600;    // [b][i][s] : 4*80*80

    const int r   = blockIdx.x;
    const int tid = threadIdx.x;

    for (int n = tid; n < 25600; n += 640) fs[n] = features[n];
    for (int n = tid; n < 25600; n += 640) {
        int j = n / 6400, rem = n % 6400, i = rem / 80, o = rem % 80;
        ws[n] = up_w[(i * 80 + o) * 800 + 200 * j + r];
    }
    __syncthreads();

    const int b  = tid / 160;
    const int oh = (tid % 160) / 80;
    const int q  = tid % 80;
    const int t  = 200 * q + r;

    ull acc[20];
    #pragma unroll
    for (int o2 = 0; o2 < 20; o2++)
        acc[o2] = pk2(__ldg(&up_b[oh * 40 + 2 * o2]), __ldg(&up_b[oh * 40 + 2 * o2 + 1]));

    #pragma unroll
    for (int j = 0; j < 4; j++) {
        int s = q - j;
        if (s >= 0) {
            const float* fsb = fs + b * 6400 + s;
            const float* wsj = ws + j * 6400 + oh * 40;
            #pragma unroll 2
            for (int i = 0; i < 80; i++) {
                ull f = bcast2(fsb[i * 80]);
                const ull* w = (const ull*)(wsj + i * 80);
                #pragma unroll
                for (int o2 = 0; o2 < 20; o2++) ffma2(acc[o2], w[o2], f);
            }
        }
    }
    float* outp = g_cond + (size_t)(b * 80 + oh * 40) * TN + t;
    #pragma unroll
    for (int o2 = 0; o2 < 20; o2++) {
        float2 v = up2(acc[o2]);
        outp[(size_t)(2 * o2) * TN]     = v.x;
        outp[(size_t)(2 * o2 + 1) * TN] = v.y;
    }
}

// ===========================================================================
// Kernel 2: embedding gather  x0[b][k][t] = emb[fi[b][t]][k]
// ===========================================================================
__global__ void k_embed(const int* __restrict__ fi,
                        const float* __restrict__ emb)
{
    int b = blockIdx.y;
    int t = blockIdx.x * 256 + threadIdx.x;
    if (t >= TN) return;
    int idx = fi[b * TN + t];
    const float* row = emb + idx * 64;
    float* out = g_x0 + (size_t)(b * 64) * TN + t;
    #pragma unroll
    for (int k = 0; k < 64; k++) out[(size_t)k * TN] = __ldg(row + k);
}

// ===========================================================================
// Kernel 3: gated WaveNet layer (512 thr), ROW-PACKED FFMA2.
//   tx = tid&31 -> 4 t, oy = tid>>5 -> rows ro..ro+3 (tanh) + 64+ro.. (sig).
//   Accumulators packed over row pairs -> weight ull pairs load DIRECTLY
//   from transposed smem (no movs); only 8 x-scalars/k need bcast.
// ===========================================================================
#define L_DW0   0              // dw0T [k][128]
#define L_DW1   8192           // dw1T [k][128]
#define L_CW    16384          // cwT  [c][128]
#define L_RW    26624          // rwT  [k][64]
#define L_GB    30720
#define L_RB    30848
#define L_XE    30912          // [64][256]
#define L_SC    47296          // [80][128]  (reused as acts tile [64][128])
#define LAYER_SMEM_FLOATS 57536

__global__ __launch_bounds__(512, 1)
void k_layer(const float* __restrict__ dil_w, const float* __restrict__ dil_b,
             const float* __restrict__ cond_w, const float* __restrict__ cond_b,
             const float* __restrict__ res_w,  const float* __restrict__ res_b,
             int li)
{
    extern __shared__ float sm[];
    float* dw0 = sm + L_DW0;
    float* dw1 = sm + L_DW1;
    float* cw  = sm + L_CW;
    float* rw  = sm + L_RW;
    float* gb  = sm + L_GB;
    float* rb  = sm + L_RB;
    float* xe  = sm + L_XE;
    float* sc  = sm + L_SC;
    float* sa  = sm + L_SC;     // overlapped, separated by a barrier

    const int tid = threadIdx.x;
    const int t0  = blockIdx.x * TT;
    const int b   = blockIdx.y;
    const int d   = 1 << (li & 7);
    const int has_res = (li < NLN - 1);

    const float* xin  = (li & 1) ? g_x1 : g_x0;
    float*       xout = (li & 1) ? g_x0 : g_x1;
    float*       acts = g_acts + (size_t)li * BN * NRN * TN;

    const float* dwb = dil_w + (size_t)li * 16384;
    const float* dbb = dil_b + li * 128;
    const float* cwb = cond_w + (size_t)li * 128 * 80;
    const float* cbb = cond_b + li * 128;

    // ---- staging (weights transposed into smem) ----
    for (int n = tid; n < 8192; n += 512) {
        int k = n >> 7, row = n & 127;
        float2 v = ((const float2*)dwb)[row * 64 + k];
        dw0[n] = v.x; dw1[n] = v.y;          // n = k*128 + row
    }
    for (int n = tid; n < 10240; n += 512) {
        int c = n >> 7, row = n & 127;
        cw[n] = cwb[row * 80 + c];           // n = c*128 + row
    }
    if (has_res) {
        const float* rwb = res_w + (size_t)li * 4096;
        for (int n = tid; n < 4096; n += 512) {
            int k = n >> 6, row = n & 63;
            rw[n] = rwb[row * 64 + k];       // n = k*64 + row
        }
        if (tid < 64) rb[tid] = res_b[li * 64 + tid];
    }
    if (tid < 128) gb[tid] = dbb[tid] + cbb[tid];

    if (t0 == 0) {
        for (int n = tid; n < 64 * 256; n += 512) {
            int k = n >> 8, tt = n & 255;
            int gt = t0 - 128 + tt;
            xe[n] = (gt >= 0) ? xin[(size_t)(b * 64 + k) * TN + gt] : 0.0f;
        }
    } else {
        for (int n = tid * 4; n < 64 * 256; n += 2048) {
            int k = n >> 8, tt = n & 255;
            *(float4*)&xe[n] = *(const float4*)&xin[(size_t)(b * 64 + k) * TN + t0 - 128 + tt];
        }
    }
    for (int n = tid * 4; n < 80 * TT; n += 2048) {
        int c = n >> 7, tt = n & 127;
        *(float4*)&sc[n] = *(const float4*)&g_cond[(size_t)(b * 80 + c) * TN + t0 + tt];
    }
    __syncthreads();

    const int tx = tid & 31, oy = tid >> 5;   // oy 0..15, warp-uniform
    const int c0 = tx * 4;
    const int ro = 4 * oy;                    // first of this thread's 4 rows

    // row-pair accumulators: xt01[t]=(rows ro,ro+1), xt23=(ro+2,ro+3); sig same
    ull at01[4], at23[4], as01[4], as23[4];
    {
        ull bt01 = *(const ull*)&gb[ro];
        ull bt23 = *(const ull*)&gb[ro + 2];
        ull bs01 = *(const ull*)&gb[64 + ro];
        ull bs23 = *(const ull*)&gb[64 + ro + 2];
        #pragma unroll
        for (int t = 0; t < 4; t++) {
            at01[t] = bt01; at23[t] = bt23;
            as01[t] = bs01; as23[t] = bs23;
        }
    }

    // ---- dilated-pair GEMM (K=64, two operands per k) ----
    const int dm4 = (d & 3) == 0;
    #pragma unroll 2
    for (int k = 0; k < 64; k++) {
        const float* xr = xe + k * 256;
        float4 xc4 = *(const float4*)&xr[128 + c0];
        float xp[4];
        if (dm4) {
            float4 v = *(const float4*)&xr[128 - d + c0];
            xp[0] = v.x; xp[1] = v.y; xp[2] = v.z; xp[3] = v.w;
        } else {
            float4 f4a = *(const float4*)&xr[124 + c0];   // t-4..t-1
            if (d == 2) { xp[0] = f4a.z; xp[1] = f4a.w; xp[2] = xc4.x; xp[3] = xc4.y; }
            else        { xp[0] = f4a.w; xp[1] = xc4.x; xp[2] = xc4.y; xp[3] = xc4.z; }
        }
        float xcv[4] = { xc4.x, xc4.y, xc4.z, xc4.w };
        // weight row-pairs load directly (warp-uniform broadcast LDS.128)
        ulonglong2 w0t = *(const ulonglong2*)&dw0[k * 128 + ro];
        ulonglong2 w0s = *(const ulonglong2*)&dw0[k * 128 + 64 + ro];
        ulonglong2 w1t = *(const ulonglong2*)&dw1[k * 128 + ro];
        ulonglong2 w1s = *(const ulonglong2*)&dw1[k * 128 + 64 + ro];
        #pragma unroll
        for (int t = 0; t < 4; t++) {
            ull xb = bcast2(xcv[t]);
            ffma2(at01[t], w1t.x, xb);  ffma2(at23[t], w1t.y, xb);
            ffma2(as01[t], w1s.x, xb);  ffma2(as23[t], w1s.y, xb);
            ull pb = bcast2(xp[t]);
            ffma2(at01[t], w0t.x, pb);  ffma2(at23[t], w0t.y, pb);
            ffma2(as01[t], w0s.x, pb);  ffma2(as23[t], w0s.y, pb);
        }
    }

    // ---- cond GEMM (K=80) ----
    #pragma unroll 2
    for (int c = 0; c < 80; c++) {
        const float* scr = sc + c * TT;
        float4 xc4 = *(const float4*)&scr[c0];
        float xcv[4] = { xc4.x, xc4.y, xc4.z, xc4.w };
        ulonglong2 wt = *(const ulonglong2*)&cw[c * 128 + ro];
        ulonglong2 wg = *(const ulonglong2*)&cw[c * 128 + 64 + ro];
        #pragma unroll
        for (int t = 0; t < 4; t++) {
            ull xb = bcast2(xcv[t]);
            ffma2(at01[t], wt.x, xb);  ffma2(at23[t], wt.y, xb);
            ffma2(as01[t], wg.x, xb);  ffma2(as23[t], wg.y, xb);
        }
    }

    // ---- gating:  av[rr][t] for rows ro+rr ----
    float av[4][4];
    #pragma unroll
    for (int t = 0; t < 4; t++) {
        float2 a01 = up2(at01[t]), a23 = up2(at23[t]);
        float2 s01 = up2(as01[t]), s23 = up2(as23[t]);
        av[0][t] = fast_tanh(a01.x) * fast_sigmoid(s01.x);
        av[1][t] = fast_tanh(a01.y) * fast_sigmoid(s01.y);
        av[2][t] = fast_tanh(a23.x) * fast_sigmoid(s23.x);
        av[3][t] = fast_tanh(a23.y) * fast_sigmoid(s23.y);
    }

    __syncthreads();   // done reading sc; region becomes sa

    #pragma unroll
    for (int rr = 0; rr < 4; rr++) {
        int row = ro + rr;
        float4 q0 = make_float4(av[rr][0], av[rr][1], av[rr][2], av[rr][3]);
        *(float4*)&sa[row * TT + c0] = q0;
        *(float4*)&(acts + (size_t)(b * 64 + row) * TN + t0)[c0] = q0;
    }
    if (!has_res) return;
    __syncthreads();

    // ---- residual GEMM (K=64) + x add (row-pair packed) ----
    ull rc01[4], rc23[4];
    {
        ull b01 = *(const ull*)&rb[ro];
        ull b23 = *(const ull*)&rb[ro + 2];
        #pragma unroll
        for (int t = 0; t < 4; t++) { rc01[t] = b01; rc23[t] = b23; }
    }
    #pragma unroll 2
    for (int k = 0; k < 64; k++) {
        const float* ar = sa + k * TT;
        float4 a4 = *(const float4*)&ar[c0];
        float avv[4] = { a4.x, a4.y, a4.z, a4.w };
        ulonglong2 wr = *(const ulonglong2*)&rw[k * 64 + ro];
        #pragma unroll
        for (int t = 0; t < 4; t++) {
            ull ab = bcast2(avv[t]);
            ffma2(rc01[t], wr.x, ab);
            ffma2(rc23[t], wr.y, ab);
        }
    }
    {
        // unpack row-pair accumulators into per-row t-vectors, add x, store
        float rcv[4][4];
        #pragma unroll
        for (int t = 0; t < 4; t++) {
            float2 r01 = up2(rc01[t]), r23 = up2(rc23[t]);
            rcv[0][t] = r01.x; rcv[1][t] = r01.y;
            rcv[2][t] = r23.x; rcv[3][t] = r23.y;
        }
        #pragma unroll
        for (int rr = 0; rr < 4; rr++) {
            int row = ro + rr;
            float4 xv = *(const float4*)&xe[row * 256 + 128 + c0];
            float4 o;
            o.x = rcv[rr][0] + xv.x;  o.y = rcv[rr][1] + xv.y;
            o.z = rcv[rr][2] + xv.z;  o.w = rcv[rr][3] + xv.w;
            *(float4*)&(xout + (size_t)(b * 64 + row) * TN + t0)[c0] = o;
        }
    }
}

// ===========================================================================
// Kernel 4: generic 128-row x 128-t GEMM over K = kchunks*64 (512 thr, FFMA2).
//   (R6 version — coalesced staging, [row][k] A layout.)
// ===========================================================================
#define GEMM_SMEM_FLOATS (8192 + 8192 + 128)
__global__ __launch_bounds__(512, 1)
void k_gemm(const float* __restrict__ A,
            float* __restrict__ dptr,            // only for dsel==2
            const float* __restrict__ biassrc,   // skip_b or nullptr
            int kchunks, int as_r, int as_c,
            long bs_b, long bs_c,
            int bsel, int dsel, int do_relu)
{
    extern __shared__ float sm[];
    float* wA    = sm;            // [128][64]
    float* sB    = sm + 8192;     // [64][128]
    float* sbias = sm + 16384;    // [128]

    const int tid = threadIdx.x;
    const int t0  = blockIdx.x * TT;
    const int mh  = blockIdx.y;
    const int b   = blockIdx.z;

    const float* Bsrc = (bsel == 0) ? g_acts : (bsel == 1) ? g_h1 : g_h2;
    float* D = (dsel == 0) ? g_h1 : (dsel == 1) ? g_h2 : dptr;

    if (tid < 128) {
        float s = 0.0f;
        if (biassrc)
            for (int i = 0; i < 16; i++) s += biassrc[i * 256 + mh * 128 + tid];
        sbias[tid] = s;
    }

    const int tx = tid & 15, oy = tid >> 4;   // oy 0..31, rows oy*4+rr
    const int c0 = tx * 4, c1 = 64 + tx * 4;

    ull acc[4][4];
    #pragma unroll
    for (int rr = 0; rr < 4; rr++)
        #pragma unroll
        for (int p = 0; p < 4; p++) acc[rr][p] = 0ULL;

    for (int ci = 0; ci < kchunks; ci++) {
        __syncthreads();
        const float* Ab = A + (size_t)(mh * 128) * as_r + (size_t)ci * as_c;
        for (int n = tid * 4; n < 8192; n += 2048) {
            int r = n >> 6, kk = n & 63;
            *(float4*)&wA[n] = *(const float4*)&Ab[(size_t)r * as_r + kk];
        }
        const float* Bb = Bsrc + (long)b * bs_b + (long)ci * bs_c + t0;
        for (int n = tid * 4; n < 8192; n += 2048) {
            int kk = n >> 7, tt = n & 127;
            *(float4*)&sB[n] = *(const float4*)&Bb[(size_t)kk * TN + tt];
        }
        __syncthreads();

        #pragma unroll 2
        for (int k = 0; k < 64; k++) {
            const float* br = sB + k * TT;
            ulonglong2 v0 = *(const ulonglong2*)&br[c0];
            ulonglong2 v1 = *(const ulonglong2*)&br[c1];
            ull bv[4] = { v0.x, v0.y, v1.x, v1.y };
            #pragma unroll
            for (int rr = 0; rr < 4; rr++) {
                ull a = bcast2(wA[(oy * 4 + rr) * 64 + k]);
                #pragma unroll
                for (int p = 0; p < 4; p++) ffma2(acc[rr][p], a, bv[p]);
            }
        }
    }

    #pragma unroll
    for (int rr = 0; rr < 4; rr++) {
        int row = oy * 4 + rr;
        float bias = sbias[row];
        float v[8];
        #pragma unroll
        for (int p = 0; p < 4; p++) {
            float2 f = up2(acc[rr][p]);
            v[2 * p]     = f.x + bias;
            v[2 * p + 1] = f.y + bias;
        }
        if (do_relu) {
            #pragma unroll
            for (int j = 0; j < 8; j++) v[j] = fmaxf(v[j], 0.0f);
        }
        size_t rbase = (size_t)(b * 256 + mh * 128 + row) * TN;
        if (dsel != 2) {
            *(float4*)&D[rbase + t0 + c0] = make_float4(v[0], v[1], v[2], v[3]);
            *(float4*)&D[rbase + t0 + c1] = make_float4(v[4], v[5], v[6], v[7]);
        } else {
            #pragma unroll
            for (int j = 0; j < 8; j++) {
                int t = t0 + ((j < 4) ? c0 + j : c1 + j - 4);
                if (t + 1 < TN) D[rbase + t + 1] = v[j];
                if (t == 0)     D[rbase] = 0.0f;
            }
        }
    }
}

// ===========================================================================
// launcher
// ===========================================================================
extern "C" void kernel_launch(void* const* d_in, const int* in_sizes, int n_in,
                              void* d_out, int out_size)
{
    const float* features = (const float*)d_in[0];
    const int*   fwd      = (const int*)  d_in[1];
    const float* emb      = (const float*)d_in[2];
    const float* up_w     = (const float*)d_in[3];
    const float* up_b     = (const float*)d_in[4];
    const float* cond_w   = (const float*)d_in[5];
    const float* cond_b   = (const float*)d_in[6];
    const float* dil_w    = (const float*)d_in[7];
    const float* dil_b    = (const float*)d_in[8];
    const float* res_w    = (const float*)d_in[9];
    const float* res_b    = (const float*)d_in[10];
    const float* skip_w   = (const float*)d_in[11];
    const float* skip_b   = (const float*)d_in[12];
    const float* out_w    = (const float*)d_in[13];
    const float* end_w    = (const float*)d_in[14];
    float* out = (float*)d_out;

    cudaFuncSetAttribute(k_upsample, cudaFuncAttributeMaxDynamicSharedMemorySize,
                         UPS_SMEM_FLOATS * 4);
    cudaFuncSetAttribute(k_layer, cudaFuncAttributeMaxDynamicSharedMemorySize,
                         LAYER_SMEM_FLOATS * 4);
    cudaFuncSetAttribute(k_gemm, cudaFuncAttributeMaxDynamicSharedMemorySize,
                         GEMM_SMEM_FLOATS * 4);

    k_upsample<<<200, 640, UPS_SMEM_FLOATS * 4>>>(features, up_w, up_b);
    k_embed<<<dim3((TN + 255) / 256, BN), 256>>>(fwd, emb);

    for (int i = 0; i < NLN; i++) {
        k_layer<<<dim3(TN / TT, BN), 512, LAYER_SMEM_FLOATS * 4>>>(
            dil_w, dil_b, cond_w, cond_b, res_w, res_b, i);
    }

    // skip-sum GEMM: h1 = relu(SW[256x1024] @ ACTS + sum_i skip_b)
    k_gemm<<<dim3(TN / TT, 2, BN), 512, GEMM_SMEM_FLOATS * 4>>>(
        skip_w, nullptr, skip_b,
        /*kchunks=*/16, /*as_r=*/64, /*as_c=*/16384,
        /*bs_b=*/(long)64 * TN, /*bs_c=*/(long)4 * 64 * TN,
        /*bsel=*/0, /*dsel=*/0, /*relu=*/1);

    // h2 = relu(out_w @ h1)
    k_gemm<<<dim3(TN / TT, 2, BN), 512, GEMM_SMEM_FLOATS * 4>>>(
        out_w, nullptr, nullptr,
        /*kchunks=*/4, /*as_r=*/256, /*as_c=*/64,
        /*bs_b=*/(long)256 * TN, /*bs_c=*/(long)64 * TN,
        /*bsel=*/1, /*dsel=*/1, /*relu=*/1);

    // out = shift_right(end_w @ h2)
    k_gemm<<<dim3(TN / TT, 2, BN), 512, GEMM_SMEM_FLOATS * 4>>>(
        end_w, out, nullptr,
        /*kchunks=*/4, /*as_r=*/256, /*as_c=*/64,
        /*bs_b=*/(long)256 * TN, /*bs_c=*/(long)64 * TN,
        /*bsel=*/2, /*dsel=*/2, /*relu=*/0);
}

// round 11
// speedup vs baseline: 1.7098x; 1.7098x over previous
#include <cuda_runtime.h>
#include <math.h>

// ---------------- problem constants ----------------
#define BN   4
#define TN   16000
#define NCN  80
#define NRN  64
#define NLN  16
#define TT   128     // t-tile for layer + gemm kernels
#define NUNITS 500   // 125 t-tiles * 4 batches
#define PGRID  148   // persistent grid for k_layer

// ---------------- device scratch (static, no dynamic alloc) ----------------
__device__ float g_cond[BN * NCN * TN];            //  [b][c][t]   20.5 MB
__device__ float g_x0  [BN * NRN * TN];            //  [b][k][t]   16.4 MB
__device__ float g_x1  [BN * NRN * TN];
__device__ float g_acts[NLN * BN * NRN * TN];      //  [i][b][k][t] 262 MB
__device__ float g_h1  [BN * 256 * TN];            //  [b][o][t]   65.5 MB
__device__ float g_h2  [BN * 256 * TN];

typedef unsigned long long ull;

// ---------------- packed f32x2 helpers (sm_103a FFMA2) ----------------
__device__ __forceinline__ void ffma2(ull& d, ull a, ull b) {
    asm("fma.rn.f32x2 %0, %1, %2, %0;" : "+l"(d) : "l"(a), "l"(b));
}
__device__ __forceinline__ ull pk2(float x, float y) {
    ull r; asm("mov.b64 %0, {%1, %2};" : "=l"(r) : "f"(x), "f"(y)); return r;
}
__device__ __forceinline__ ull bcast2(float x) {
    ull r; asm("mov.b64 %0, {%1, %1};" : "=l"(r) : "f"(x)); return r;
}
__device__ __forceinline__ float2 up2(ull v) {
    float2 f; asm("mov.b64 {%0, %1}, %2;" : "=f"(f.x), "=f"(f.y) : "l"(v)); return f;
}

// ---------------- fast activations ----------------
__device__ __forceinline__ float fast_sigmoid(float x) {
    return __fdividef(1.0f, 1.0f + __expf(-x));
}
__device__ __forceinline__ float fast_tanh(float x) {
    float ax = fabsf(x);
    float e  = __expf(-2.0f * ax);
    float t  = __fdividef(1.0f - e, 1.0f + e);
    return copysignf(t, x);
}

// ===========================================================================
// Kernel 1: transposed-conv upsampler by output phase (640 thr, FFMA2).
// ===========================================================================
#define UPS_SMEM_FLOATS (25600 + 25600)
__global__ __launch_bounds__(640, 1)
void k_upsample(const float* __restrict__ features,
                const float* __restrict__ up_w,
                const float* __restrict__ up_b)
{
    extern __shared__ float sm[];
    float* ws = sm;            // [j][i][o] : 4*80*80
    float* fs = sm + 25600;    // [b][i][s] : 4*80*80

    const int r   = blockIdx.x;
    const int tid = threadIdx.x;

    for (int n = tid; n < 25600; n += 640) fs[n] = features[n];
    for (int n = tid; n < 25600; n += 640) {
        int j = n / 6400, rem = n % 6400, i = rem / 80, o = rem % 80;
        ws[n] = up_w[(i * 80 + o) * 800 + 200 * j + r];
    }
    __syncthreads();

    const int b  = tid / 160;
    const int oh = (tid % 160) / 80;
    const int q  = tid % 80;
    const int t  = 200 * q + r;

    ull acc[20];
    #pragma unroll
    for (int o2 = 0; o2 < 20; o2++)
        acc[o2] = pk2(__ldg(&up_b[oh * 40 + 2 * o2]), __ldg(&up_b[oh * 40 + 2 * o2 + 1]));

    #pragma unroll
    for (int j = 0; j < 4; j++) {
        int s = q - j;
        if (s >= 0) {
            const float* fsb = fs + b * 6400 + s;
            const float* wsj = ws + j * 6400 + oh * 40;
            #pragma unroll 2
            for (int i = 0; i < 80; i++) {
                ull f = bcast2(fsb[i * 80]);
                const ull* w = (const ull*)(wsj + i * 80);
                #pragma unroll
                for (int o2 = 0; o2 < 20; o2++) ffma2(acc[o2], w[o2], f);
            }
        }
    }
    float* outp = g_cond + (size_t)(b * 80 + oh * 40) * TN + t;
    #pragma unroll
    for (int o2 = 0; o2 < 20; o2++) {
        float2 v = up2(acc[o2]);
        outp[(size_t)(2 * o2) * TN]     = v.x;
        outp[(size_t)(2 * o2 + 1) * TN] = v.y;
    }
}

// ===========================================================================
// Kernel 2: embedding gather  x0[b][k][t] = emb[fi[b][t]][k]
// ===========================================================================
__global__ void k_embed(const int* __restrict__ fi,
                        const float* __restrict__ emb)
{
    int b = blockIdx.y;
    int t = blockIdx.x * 256 + threadIdx.x;
    if (t >= TN) return;
    int idx = fi[b * TN + t];
    const float* row = emb + idx * 64;
    float* out = g_x0 + (size_t)(b * 64) * TN + t;
    #pragma unroll
    for (int k = 0; k < 64; k++) out[(size_t)k * TN] = __ldg(row + k);
}

// ===========================================================================
// Kernel 3: gated WaveNet layer — PERSISTENT (148 CTAs x 512 thr).
//   Weights staged ONCE per CTA; each CTA strides over (tile,b) units.
//   Per-thread: tx=tid&31 -> 4 t, oy=tid>>5 -> 4 tanh + 4 sigmoid rows
//   (oy warp-uniform -> all weight LDS are broadcasts). R8 math layout.
// ===========================================================================
#define L_DW0   0              // dw0T [k][128]
#define L_DW1   8192           // dw1T [k][128]
#define L_CW    16384          // cwT  [c][128]
#define L_RW    26624          // rwT  [k][64]
#define L_GB    30720
#define L_RB    30848
#define L_XE    30912          // [64][256]
#define L_SC    47296          // [80][128]  (reused as acts tile [64][128])
#define LAYER_SMEM_FLOATS 57536

__global__ __launch_bounds__(512, 1)
void k_layer(const float* __restrict__ dil_w, const float* __restrict__ dil_b,
             const float* __restrict__ cond_w, const float* __restrict__ cond_b,
             const float* __restrict__ res_w,  const float* __restrict__ res_b,
             int li)
{
    extern __shared__ float sm[];
    float* dw0 = sm + L_DW0;
    float* dw1 = sm + L_DW1;
    float* cw  = sm + L_CW;
    float* rw  = sm + L_RW;
    float* gb  = sm + L_GB;
    float* rb  = sm + L_RB;
    float* xe  = sm + L_XE;
    float* sc  = sm + L_SC;
    float* sa  = sm + L_SC;     // overlapped, separated by barriers

    const int tid = threadIdx.x;
    const int d   = 1 << (li & 7);
    const int has_res = (li < NLN - 1);

    const float* xin  = (li & 1) ? g_x1 : g_x0;
    float*       xout = (li & 1) ? g_x0 : g_x1;
    float*       actsbase = g_acts + (size_t)li * BN * NRN * TN;

    const float* dwb = dil_w + (size_t)li * 16384;
    const float* dbb = dil_b + li * 128;
    const float* cwb = cond_w + (size_t)li * 128 * 80;
    const float* cbb = cond_b + li * 128;

    // ---- one-time weight staging (transposed into smem) ----
    for (int n = tid; n < 8192; n += 512) {
        int k = n >> 7, row = n & 127;
        float2 v = ((const float2*)dwb)[row * 64 + k];
        dw0[n] = v.x; dw1[n] = v.y;          // n = k*128 + row
    }
    for (int n = tid; n < 10240; n += 512) {
        int c = n >> 7, row = n & 127;
        cw[n] = cwb[row * 80 + c];           // n = c*128 + row
    }
    if (has_res) {
        const float* rwb = res_w + (size_t)li * 4096;
        for (int n = tid; n < 4096; n += 512) {
            int k = n >> 6, row = n & 63;
            rw[n] = rwb[row * 64 + k];       // n = k*64 + row
        }
        if (tid < 64) rb[tid] = res_b[li * 64 + tid];
    }
    if (tid < 128) gb[tid] = dbb[tid] + cbb[tid];

    const int tx = tid & 31, oy = tid >> 5;   // oy 0..15, warp-uniform
    const int c0 = tx * 4;
    const int ro = 4 * oy;

    // ---- persistent unit loop ----
    for (int u = blockIdx.x; u < NUNITS; u += PGRID) {
        const int b  = u & 3;
        const int t0 = (u >> 2) * TT;
        float* acts = actsbase;

        __syncthreads();   // protect sa (prev unit) before restaging sc/xe

        if (t0 == 0) {
            for (int n = tid; n < 64 * 256; n += 512) {
                int k = n >> 8, tt = n & 255;
                int gt = t0 - 128 + tt;
                xe[n] = (gt >= 0) ? xin[(size_t)(b * 64 + k) * TN + gt] : 0.0f;
            }
        } else {
            for (int n = tid * 4; n < 64 * 256; n += 2048) {
                int k = n >> 8, tt = n & 255;
                *(float4*)&xe[n] = *(const float4*)&xin[(size_t)(b * 64 + k) * TN + t0 - 128 + tt];
            }
        }
        for (int n = tid * 4; n < 80 * TT; n += 2048) {
            int c = n >> 7, tt = n & 127;
            *(float4*)&sc[n] = *(const float4*)&g_cond[(size_t)(b * 80 + c) * TN + t0 + tt];
        }
        __syncthreads();

        ull at[4][2], as_[4][2];
        #pragma unroll
        for (int rr = 0; rr < 4; rr++) {
            ull bt = bcast2(gb[ro + rr]);
            ull bs = bcast2(gb[64 + ro + rr]);
            at[rr][0] = bt; at[rr][1] = bt;
            as_[rr][0] = bs; as_[rr][1] = bs;
        }

        // ---- dilated-pair GEMM (K=64, two operands per k) ----
        const int dm4 = (d & 3) == 0;
        #pragma unroll 2
        for (int k = 0; k < 64; k++) {
            const float* xr = xe + k * 256;
            ull xc[2], xp[2];
            {
                ulonglong2 v0 = *(const ulonglong2*)&xr[128 + c0];
                xc[0] = v0.x; xc[1] = v0.y;
            }
            if (dm4) {
                ulonglong2 v0 = *(const ulonglong2*)&xr[128 - d + c0];
                xp[0] = v0.x; xp[1] = v0.y;
            } else if (d == 2) {
                xp[0] = *(const ull*)&xr[126 + c0];
                xp[1] = *(const ull*)&xr[128 + c0];
            } else { // d == 1
                xp[0] = pk2(xr[127 + c0], xr[128 + c0]);
                xp[1] = pk2(xr[129 + c0], xr[130 + c0]);
            }
            float4 w0t = *(const float4*)&dw0[k * 128 + ro];
            float4 w0s = *(const float4*)&dw0[k * 128 + 64 + ro];
            float4 w1t = *(const float4*)&dw1[k * 128 + ro];
            float4 w1s = *(const float4*)&dw1[k * 128 + 64 + ro];
            const float* w0tp = (const float*)&w0t;
            const float* w0sp = (const float*)&w0s;
            const float* w1tp = (const float*)&w1t;
            const float* w1sp = (const float*)&w1s;
            #pragma unroll
            for (int rr = 0; rr < 4; rr++) {
                ull b0t = bcast2(w0tp[rr]), b1t = bcast2(w1tp[rr]);
                ull b0s = bcast2(w0sp[rr]), b1s = bcast2(w1sp[rr]);
                #pragma unroll
                for (int p = 0; p < 2; p++) {
                    ffma2(at[rr][p],  b0t, xp[p]);  ffma2(at[rr][p],  b1t, xc[p]);
                    ffma2(as_[rr][p], b0s, xp[p]);  ffma2(as_[rr][p], b1s, xc[p]);
                }
            }
        }

        // ---- cond GEMM (K=80) ----
        #pragma unroll 2
        for (int c = 0; c < 80; c++) {
            const float* scr = sc + c * TT;
            ulonglong2 v0 = *(const ulonglong2*)&scr[c0];
            ull xc[2] = { v0.x, v0.y };
            float4 wt4 = *(const float4*)&cw[c * 128 + ro];
            float4 wg4 = *(const float4*)&cw[c * 128 + 64 + ro];
            const float* wtp = (const float*)&wt4;
            const float* wgp = (const float*)&wg4;
            #pragma unroll
            for (int rr = 0; rr < 4; rr++) {
                ull wt = bcast2(wtp[rr]);
                ull wg = bcast2(wgp[rr]);
                #pragma unroll
                for (int p = 0; p < 2; p++) {
                    ffma2(at[rr][p], wt, xc[p]);
                    ffma2(as_[rr][p], wg, xc[p]);
                }
            }
        }

        // ---- gating ----
        float av[4][4];
        #pragma unroll
        for (int rr = 0; rr < 4; rr++)
            #pragma unroll
            for (int p = 0; p < 2; p++) {
                float2 t2 = up2(at[rr][p]);
                float2 s2 = up2(as_[rr][p]);
                av[rr][2 * p]     = fast_tanh(t2.x) * fast_sigmoid(s2.x);
                av[rr][2 * p + 1] = fast_tanh(t2.y) * fast_sigmoid(s2.y);
            }

        __syncthreads();   // done reading sc; region becomes sa

        #pragma unroll
        for (int rr = 0; rr < 4; rr++) {
            int row = ro + rr;
            float4 q0 = make_float4(av[rr][0], av[rr][1], av[rr][2], av[rr][3]);
            *(float4*)&sa[row * TT + c0] = q0;
            *(float4*)&(acts + (size_t)(b * 64 + row) * TN + t0)[c0] = q0;
        }
        if (!has_res) continue;
        __syncthreads();

        // ---- residual GEMM (K=64) + x add ----
        ull rc[4][2];
        #pragma unroll
        for (int rr = 0; rr < 4; rr++) {
            ull bv = bcast2(rb[ro + rr]);
            rc[rr][0] = bv; rc[rr][1] = bv;
        }
        #pragma unroll 2
        for (int k = 0; k < 64; k++) {
            const float* ar = sa + k * TT;
            ulonglong2 v0 = *(const ulonglong2*)&ar[c0];
            float4 wr4 = *(const float4*)&rw[k * 64 + ro];
            const float* wrp = (const float*)&wr4;
            #pragma unroll
            for (int rr = 0; rr < 4; rr++) {
                ull w = bcast2(wrp[rr]);
                ffma2(rc[rr][0], w, v0.x);
                ffma2(rc[rr][1], w, v0.y);
            }
        }
        #pragma unroll
        for (int rr = 0; rr < 4; rr++) {
            int row = ro + rr;
            float4 xv = *(const float4*)&xe[row * 256 + 128 + c0];
            float2 r0 = up2(rc[rr][0]), r1 = up2(rc[rr][1]);
            float4 o;
            o.x = r0.x + xv.x;  o.y = r0.y + xv.y;
            o.z = r1.x + xv.z;  o.w = r1.y + xv.w;
            *(float4*)&(xout + (size_t)(b * 64 + row) * TN + t0)[c0] = o;
        }
    }
}

// ===========================================================================
// Kernel 4: generic 128-row x 128-t GEMM over K = kchunks*64 (512 thr, FFMA2).
//   Coalesced staging, [row][k] A layout (R4/R8-proven version).
// ===========================================================================
#define GEMM_SMEM_FLOATS (8192 + 8192 + 128)
__global__ __launch_bounds__(512, 1)
void k_gemm(const float* __restrict__ A,
            float* __restrict__ dptr,            // only for dsel==2
            const float* __restrict__ biassrc,   // skip_b or nullptr
            int kchunks, int as_r, int as_c,
            long bs_b, long bs_c,
            int bsel, int dsel, int do_relu)
{
    extern __shared__ float sm[];
    float* wA    = sm;            // [128][64]
    float* sB    = sm + 8192;     // [64][128]
    float* sbias = sm + 16384;    // [128]

    const int tid = threadIdx.x;
    const int t0  = blockIdx.x * TT;
    const int mh  = blockIdx.y;
    const int b   = blockIdx.z;

    const float* Bsrc = (bsel == 0) ? g_acts : (bsel == 1) ? g_h1 : g_h2;
    float* D = (dsel == 0) ? g_h1 : (dsel == 1) ? g_h2 : dptr;

    if (tid < 128) {
        float s = 0.0f;
        if (biassrc)
            for (int i = 0; i < 16; i++) s += biassrc[i * 256 + mh * 128 + tid];
        sbias[tid] = s;
    }

    const int tx = tid & 15, oy = tid >> 4;   // oy 0..31, rows oy*4+rr
    const int c0 = tx * 4, c1 = 64 + tx * 4;

    ull acc[4][4];
    #pragma unroll
    for (int rr = 0; rr < 4; rr++)
        #pragma unroll
        for (int p = 0; p < 4; p++) acc[rr][p] = 0ULL;

    for (int ci = 0; ci < kchunks; ci++) {
        __syncthreads();
        const float* Ab = A + (size_t)(mh * 128) * as_r + (size_t)ci * as_c;
        for (int n = tid * 4; n < 8192; n += 2048) {
            int r = n >> 6, kk = n & 63;
            *(float4*)&wA[n] = *(const float4*)&Ab[(size_t)r * as_r + kk];
        }
        const float* Bb = Bsrc + (long)b * bs_b + (long)ci * bs_c + t0;
        for (int n = tid * 4; n < 8192; n += 2048) {
            int kk = n >> 7, tt = n & 127;
            *(float4*)&sB[n] = *(const float4*)&Bb[(size_t)kk * TN + tt];
        }
        __syncthreads();

        #pragma unroll 2
        for (int k = 0; k < 64; k++) {
            const float* br = sB + k * TT;
            ulonglong2 v0 = *(const ulonglong2*)&br[c0];
            ulonglong2 v1 = *(const ulonglong2*)&br[c1];
            ull bv[4] = { v0.x, v0.y, v1.x, v1.y };
            #pragma unroll
            for (int rr = 0; rr < 4; rr++) {
                ull a = bcast2(wA[(oy * 4 + rr) * 64 + k]);
                #pragma unroll
                for (int p = 0; p < 4; p++) ffma2(acc[rr][p], a, bv[p]);
            }
        }
    }

    #pragma unroll
    for (int rr = 0; rr < 4; rr++) {
        int row = oy * 4 + rr;
        float bias = sbias[row];
        float v[8];
        #pragma unroll
        for (int p = 0; p < 4; p++) {
            float2 f = up2(acc[rr][p]);
            v[2 * p]     = f.x + bias;
            v[2 * p + 1] = f.y + bias;
        }
        if (do_relu) {
            #pragma unroll
            for (int j = 0; j < 8; j++) v[j] = fmaxf(v[j], 0.0f);
        }
        size_t rbase = (size_t)(b * 256 + mh * 128 + row) * TN;
        if (dsel != 2) {
            *(float4*)&D[rbase + t0 + c0] = make_float4(v[0], v[1], v[2], v[3]);
            *(float4*)&D[rbase + t0 + c1] = make_float4(v[4], v[5], v[6], v[7]);
        } else {
            #pragma unroll
            for (int j = 0; j < 8; j++) {
                int t = t0 + ((j < 4) ? c0 + j : c1 + j - 4);
                if (t + 1 < TN) D[rbase + t + 1] = v[j];
                if (t == 0)     D[rbase] = 0.0f;
            }
        }
    }
}

// ===========================================================================
// launcher
// ===========================================================================
extern "C" void kernel_launch(void* const* d_in, const int* in_sizes, int n_in,
                              void* d_out, int out_size)
{
    const float* features = (const float*)d_in[0];
    const int*   fwd      = (const int*)  d_in[1];
    const float* emb      = (const float*)d_in[2];
    const float* up_w     = (const float*)d_in[3];
    const float* up_b     = (const float*)d_in[4];
    const float* cond_w   = (const float*)d_in[5];
    const float* cond_b   = (const float*)d_in[6];
    const float* dil_w    = (const float*)d_in[7];
    const float* dil_b    = (const float*)d_in[8];
    const float* res_w    = (const float*)d_in[9];
    const float* res_b    = (const float*)d_in[10];
    const float* skip_w   = (const float*)d_in[11];
    const float* skip_b   = (const float*)d_in[12];
    const float* out_w    = (const float*)d_in[13];
    const float* end_w    = (const float*)d_in[14];
    float* out = (float*)d_out;

    cudaFuncSetAttribute(k_upsample, cudaFuncAttributeMaxDynamicSharedMemorySize,
                         UPS_SMEM_FLOATS * 4);
    cudaFuncSetAttribute(k_layer, cudaFuncAttributeMaxDynamicSharedMemorySize,
                         LAYER_SMEM_FLOATS * 4);
    cudaFuncSetAttribute(k_gemm, cudaFuncAttributeMaxDynamicSharedMemorySize,
                         GEMM_SMEM_FLOATS * 4);

    k_upsample<<<200, 640, UPS_SMEM_FLOATS * 4>>>(features, up_w, up_b);
    k_embed<<<dim3((TN + 255) / 256, BN), 256>>>(fwd, emb);

    for (int i = 0; i < NLN; i++) {
        k_layer<<<PGRID, 512, LAYER_SMEM_FLOATS * 4>>>(
            dil_w, dil_b, cond_w, cond_b, res_w, res_b, i);
    }

    // skip-sum GEMM: h1 = relu(SW[256x1024] @ ACTS + sum_i skip_b)
    k_gemm<<<dim3(TN / TT, 2, BN), 512, GEMM_SMEM_FLOATS * 4>>>(
        skip_w, nullptr, skip_b,
        /*kchunks=*/16, /*as_r=*/64, /*as_c=*/16384,
        /*bs_b=*/(long)64 * TN, /*bs_c=*/(long)4 * 64 * TN,
        /*bsel=*/0, /*dsel=*/0, /*relu=*/1);

    // h2 = relu(out_w @ h1)
    k_gemm<<<dim3(TN / TT, 2, BN), 512, GEMM_SMEM_FLOATS * 4>>>(
        out_w, nullptr, nullptr,
        /*kchunks=*/4, /*as_r=*/256, /*as_c=*/64,
        /*bs_b=*/(long)256 * TN, /*bs_c=*/(long)64 * TN,
        /*bsel=*/1, /*dsel=*/1, /*relu=*/1);

    // out = shift_right(end_w @ h2)
    k_gemm<<<dim3(TN / TT, 2, BN), 512, GEMM_SMEM_FLOATS * 4>>>(
        end_w, out, nullptr,
        /*kchunks=*/4, /*as_r=*/256, /*as_c=*/64,
        /*bs_b=*/(long)256 * TN, /*bs_c=*/(long)64 * TN,
        /*bsel=*/2, /*dsel=*/2, /*relu=*/0);
}

// round 13
// speedup vs baseline: 1.8023x; 1.0541x over previous
#include <cuda_runtime.h>
#include <math.h>

// ---------------- problem constants ----------------
#define BN   4
#define TN   16000
#define NCN  80
#define NRN  64
#define NLN  16
#define TT   128     // t-tile for layer + gemm kernels
#define NUNITS 500   // 125 t-tiles * 4 batches
#define PGRID  148   // persistent grid for k_layer

// ---------------- device scratch (static, no dynamic alloc) ----------------
__device__ float g_cond[BN * NCN * TN];            //  [b][c][t]   20.5 MB
__device__ float g_x0  [BN * NRN * TN];            //  [b][k][t]   16.4 MB
__device__ float g_x1  [BN * NRN * TN];
__device__ float g_acts[NLN * BN * NRN * TN];      //  [i][b][k][t] 262 MB
__device__ float g_h1  [BN * 256 * TN];            //  [b][o][t]   65.5 MB

typedef unsigned long long ull;

// ---------------- packed f32x2 helpers (sm_103a FFMA2) ----------------
__device__ __forceinline__ void ffma2(ull& d, ull a, ull b) {
    asm("fma.rn.f32x2 %0, %1, %2, %0;" : "+l"(d) : "l"(a), "l"(b));
}
__device__ __forceinline__ ull pk2(float x, float y) {
    ull r; asm("mov.b64 %0, {%1, %2};" : "=l"(r) : "f"(x), "f"(y)); return r;
}
__device__ __forceinline__ ull bcast2(float x) {
    ull r; asm("mov.b64 %0, {%1, %1};" : "=l"(r) : "f"(x)); return r;
}
__device__ __forceinline__ float2 up2(ull v) {
    float2 f; asm("mov.b64 {%0, %1}, %2;" : "=f"(f.x), "=f"(f.y) : "l"(v)); return f;
}

// ---------------- fast activations ----------------
__device__ __forceinline__ float fast_sigmoid(float x) {
    return __fdividef(1.0f, 1.0f + __expf(-x));
}
__device__ __forceinline__ float fast_tanh(float x) {
    float ax = fabsf(x);
    float e  = __expf(-2.0f * ax);
    float t  = __fdividef(1.0f - e, 1.0f + e);
    return copysignf(t, x);
}

// ===========================================================================
// Kernel 1: transposed-conv upsampler by output phase (640 thr, FFMA2).
// ===========================================================================
#define UPS_SMEM_FLOATS (25600 + 25600)
__global__ __launch_bounds__(640, 1)
void k_upsample(const float* __restrict__ features,
                const float* __restrict__ up_w,
                const float* __restrict__ up_b)
{
    extern __shared__ float sm[];
    float* ws = sm;            // [j][i][o] : 4*80*80
    float* fs = sm + 25600;    // [b][i][s] : 4*80*80

    const int r   = blockIdx.x;
    const int tid = threadIdx.x;

    for (int n = tid; n < 25600; n += 640) fs[n] = features[n];
    for (int n = tid; n < 25600; n += 640) {
        int j = n / 6400, rem = n % 6400, i = rem / 80, o = rem % 80;
        ws[n] = up_w[(i * 80 + o) * 800 + 200 * j + r];
    }
    __syncthreads();

    const int b  = tid / 160;
    const int oh = (tid % 160) / 80;
    const int q  = tid % 80;
    const int t  = 200 * q + r;

    ull acc[20];
    #pragma unroll
    for (int o2 = 0; o2 < 20; o2++)
        acc[o2] = pk2(__ldg(&up_b[oh * 40 + 2 * o2]), __ldg(&up_b[oh * 40 + 2 * o2 + 1]));

    #pragma unroll
    for (int j = 0; j < 4; j++) {
        int s = q - j;
        if (s >= 0) {
            const float* fsb = fs + b * 6400 + s;
            const float* wsj = ws + j * 6400 + oh * 40;
            #pragma unroll 2
            for (int i = 0; i < 80; i++) {
                ull f = bcast2(fsb[i * 80]);
                const ull* w = (const ull*)(wsj + i * 80);
                #pragma unroll
                for (int o2 = 0; o2 < 20; o2++) ffma2(acc[o2], w[o2], f);
            }
        }
    }
    float* outp = g_cond + (size_t)(b * 80 + oh * 40) * TN + t;
    #pragma unroll
    for (int o2 = 0; o2 < 20; o2++) {
        float2 v = up2(acc[o2]);
        outp[(size_t)(2 * o2) * TN]     = v.x;
        outp[(size_t)(2 * o2 + 1) * TN] = v.y;
    }
}

// ===========================================================================
// Kernel 2: embedding gather  x0[b][k][t] = emb[fi[b][t]][k]
// ===========================================================================
__global__ void k_embed(const int* __restrict__ fi,
                        const float* __restrict__ emb)
{
    int b = blockIdx.y;
    int t = blockIdx.x * 256 + threadIdx.x;
    if (t >= TN) return;
    int idx = fi[b * TN + t];
    const float* row = emb + idx * 64;
    float* out = g_x0 + (size_t)(b * 64) * TN + t;
    #pragma unroll
    for (int k = 0; k < 64; k++) out[(size_t)k * TN] = __ldg(row + k);
}

// ===========================================================================
// Kernel 3: gated WaveNet layer — PERSISTENT (148 CTAs x 512 thr).
//   (R11-proven version, unchanged.)
// ===========================================================================
#define L_DW0   0              // dw0T [k][128]
#define L_DW1   8192           // dw1T [k][128]
#define L_CW    16384          // cwT  [c][128]
#define L_RW    26624          // rwT  [k][64]
#define L_GB    30720
#define L_RB    30848
#define L_XE    30912          // [64][256]
#define L_SC    47296          // [80][128]  (reused as acts tile [64][128])
#define LAYER_SMEM_FLOATS 57536

__global__ __launch_bounds__(512, 1)
void k_layer(const float* __restrict__ dil_w, const float* __restrict__ dil_b,
             const float* __restrict__ cond_w, const float* __restrict__ cond_b,
             const float* __restrict__ res_w,  const float* __restrict__ res_b,
             int li)
{
    extern __shared__ float sm[];
    float* dw0 = sm + L_DW0;
    float* dw1 = sm + L_DW1;
    float* cw  = sm + L_CW;
    float* rw  = sm + L_RW;
    float* gb  = sm + L_GB;
    float* rb  = sm + L_RB;
    float* xe  = sm + L_XE;
    float* sc  = sm + L_SC;
    float* sa  = sm + L_SC;     // overlapped, separated by barriers

    const int tid = threadIdx.x;
    const int d   = 1 << (li & 7);
    const int has_res = (li < NLN - 1);

    const float* xin  = (li & 1) ? g_x1 : g_x0;
    float*       xout = (li & 1) ? g_x0 : g_x1;
    float*       actsbase = g_acts + (size_t)li * BN * NRN * TN;

    const float* dwb = dil_w + (size_t)li * 16384;
    const float* dbb = dil_b + li * 128;
    const float* cwb = cond_w + (size_t)li * 128 * 80;
    const float* cbb = cond_b + li * 128;

    // ---- one-time weight staging (transposed into smem) ----
    for (int n = tid; n < 8192; n += 512) {
        int k = n >> 7, row = n & 127;
        float2 v = ((const float2*)dwb)[row * 64 + k];
        dw0[n] = v.x; dw1[n] = v.y;          // n = k*128 + row
    }
    for (int n = tid; n < 10240; n += 512) {
        int c = n >> 7, row = n & 127;
        cw[n] = cwb[row * 80 + c];           // n = c*128 + row
    }
    if (has_res) {
        const float* rwb = res_w + (size_t)li * 4096;
        for (int n = tid; n < 4096; n += 512) {
            int k = n >> 6, row = n & 63;
            rw[n] = rwb[row * 64 + k];       // n = k*64 + row
        }
        if (tid < 64) rb[tid] = res_b[li * 64 + tid];
    }
    if (tid < 128) gb[tid] = dbb[tid] + cbb[tid];

    const int tx = tid & 31, oy = tid >> 5;   // oy 0..15, warp-uniform
    const int c0 = tx * 4;
    const int ro = 4 * oy;

    // ---- persistent unit loop ----
    for (int u = blockIdx.x; u < NUNITS; u += PGRID) {
        const int b  = u & 3;
        const int t0 = (u >> 2) * TT;
        float* acts = actsbase;

        __syncthreads();   // protect sa (prev unit) before restaging sc/xe

        if (t0 == 0) {
            for (int n = tid; n < 64 * 256; n += 512) {
                int k = n >> 8, tt = n & 255;
                int gt = t0 - 128 + tt;
                xe[n] = (gt >= 0) ? xin[(size_t)(b * 64 + k) * TN + gt] : 0.0f;
            }
        } else {
            for (int n = tid * 4; n < 64 * 256; n += 2048) {
                int k = n >> 8, tt = n & 255;
                *(float4*)&xe[n] = *(const float4*)&xin[(size_t)(b * 64 + k) * TN + t0 - 128 + tt];
            }
        }
        for (int n = tid * 4; n < 80 * TT; n += 2048) {
            int c = n >> 7, tt = n & 127;
            *(float4*)&sc[n] = *(const float4*)&g_cond[(size_t)(b * 80 + c) * TN + t0 + tt];
        }
        __syncthreads();

        ull at[4][2], as_[4][2];
        #pragma unroll
        for (int rr = 0; rr < 4; rr++) {
            ull bt = bcast2(gb[ro + rr]);
            ull bs = bcast2(gb[64 + ro + rr]);
            at[rr][0] = bt; at[rr][1] = bt;
            as_[rr][0] = bs; as_[rr][1] = bs;
        }

        // ---- dilated-pair GEMM (K=64, two operands per k) ----
        const int dm4 = (d & 3) == 0;
        #pragma unroll 2
        for (int k = 0; k < 64; k++) {
            const float* xr = xe + k * 256;
            ull xc[2], xp[2];
            {
                ulonglong2 v0 = *(const ulonglong2*)&xr[128 + c0];
                xc[0] = v0.x; xc[1] = v0.y;
            }
            if (dm4) {
                ulonglong2 v0 = *(const ulonglong2*)&xr[128 - d + c0];
                xp[0] = v0.x; xp[1] = v0.y;
            } else if (d == 2) {
                xp[0] = *(const ull*)&xr[126 + c0];
                xp[1] = *(const ull*)&xr[128 + c0];
            } else { // d == 1
                xp[0] = pk2(xr[127 + c0], xr[128 + c0]);
                xp[1] = pk2(xr[129 + c0], xr[130 + c0]);
            }
            float4 w0t = *(const float4*)&dw0[k * 128 + ro];
            float4 w0s = *(const float4*)&dw0[k * 128 + 64 + ro];
            float4 w1t = *(const float4*)&dw1[k * 128 + ro];
            float4 w1s = *(const float4*)&dw1[k * 128 + 64 + ro];
            const float* w0tp = (const float*)&w0t;
            const float* w0sp = (const float*)&w0s;
            const float* w1tp = (const float*)&w1t;
            const float* w1sp = (const float*)&w1s;
            #pragma unroll
            for (int rr = 0; rr < 4; rr++) {
                ull b0t = bcast2(w0tp[rr]), b1t = bcast2(w1tp[rr]);
                ull b0s = bcast2(w0sp[rr]), b1s = bcast2(w1sp[rr]);
                #pragma unroll
                for (int p = 0; p < 2; p++) {
                    ffma2(at[rr][p],  b0t, xp[p]);  ffma2(at[rr][p],  b1t, xc[p]);
                    ffma2(as_[rr][p], b0s, xp[p]);  ffma2(as_[rr][p], b1s, xc[p]);
                }
            }
        }

        // ---- cond GEMM (K=80) ----
        #pragma unroll 2
        for (int c = 0; c < 80; c++) {
            const float* scr = sc + c * TT;
            ulonglong2 v0 = *(const ulonglong2*)&scr[c0];
            ull xc[2] = { v0.x, v0.y };
            float4 wt4 = *(const float4*)&cw[c * 128 + ro];
            float4 wg4 = *(const float4*)&cw[c * 128 + 64 + ro];
            const float* wtp = (const float*)&wt4;
            const float* wgp = (const float*)&wg4;
            #pragma unroll
            for (int rr = 0; rr < 4; rr++) {
                ull wt = bcast2(wtp[rr]);
                ull wg = bcast2(wgp[rr]);
                #pragma unroll
                for (int p = 0; p < 2; p++) {
                    ffma2(at[rr][p], wt, xc[p]);
                    ffma2(as_[rr][p], wg, xc[p]);
                }
            }
        }

        // ---- gating ----
        float av[4][4];
        #pragma unroll
        for (int rr = 0; rr < 4; rr++)
            #pragma unroll
            for (int p = 0; p < 2; p++) {
                float2 t2 = up2(at[rr][p]);
                float2 s2 = up2(as_[rr][p]);
                av[rr][2 * p]     = fast_tanh(t2.x) * fast_sigmoid(s2.x);
                av[rr][2 * p + 1] = fast_tanh(t2.y) * fast_sigmoid(s2.y);
            }

        __syncthreads();   // done reading sc; region becomes sa

        #pragma unroll
        for (int rr = 0; rr < 4; rr++) {
            int row = ro + rr;
            float4 q0 = make_float4(av[rr][0], av[rr][1], av[rr][2], av[rr][3]);
            *(float4*)&sa[row * TT + c0] = q0;
            *(float4*)&(acts + (size_t)(b * 64 + row) * TN + t0)[c0] = q0;
        }
        if (!has_res) continue;
        __syncthreads();

        // ---- residual GEMM (K=64) + x add ----
        ull rc[4][2];
        #pragma unroll
        for (int rr = 0; rr < 4; rr++) {
            ull bv = bcast2(rb[ro + rr]);
            rc[rr][0] = bv; rc[rr][1] = bv;
        }
        #pragma unroll 2
        for (int k = 0; k < 64; k++) {
            const float* ar = sa + k * TT;
            ulonglong2 v0 = *(const ulonglong2*)&ar[c0];
            float4 wr4 = *(const float4*)&rw[k * 64 + ro];
            const float* wrp = (const float*)&wr4;
            #pragma unroll
            for (int rr = 0; rr < 4; rr++) {
                ull w = bcast2(wrp[rr]);
                ffma2(rc[rr][0], w, v0.x);
                ffma2(rc[rr][1], w, v0.y);
            }
        }
        #pragma unroll
        for (int rr = 0; rr < 4; rr++) {
            int row = ro + rr;
            float4 xv = *(const float4*)&xe[row * 256 + 128 + c0];
            float2 r0 = up2(rc[rr][0]), r1 = up2(rc[rr][1]);
            float4 o;
            o.x = r0.x + xv.x;  o.y = r0.y + xv.y;
            o.z = r1.x + xv.z;  o.w = r1.y + xv.w;
            *(float4*)&(xout + (size_t)(b * 64 + row) * TN + t0)[c0] = o;
        }
    }
}

// ===========================================================================
// Kernel 4: skip-sum GEMM h1 = relu(SW[128x1024] @ ACTS + bias) (R11 k_gemm,
// specialized: bsel==0/dsel==0 path only).
// ===========================================================================
#define GEMM_SMEM_FLOATS (8192 + 8192 + 128)
__global__ __launch_bounds__(512, 1)
void k_gemm(const float* __restrict__ A,
            const float* __restrict__ biassrc,   // skip_b
            int kchunks, int as_r, int as_c,
            long bs_b, long bs_c)
{
    extern __shared__ float sm[];
    float* wA    = sm;            // [128][64]
    float* sB    = sm + 8192;     // [64][128]
    float* sbias = sm + 16384;    // [128]

    const int tid = threadIdx.x;
    const int t0  = blockIdx.x * TT;
    const int mh  = blockIdx.y;
    const int b   = blockIdx.z;

    const float* Bsrc = g_acts;
    float* D = g_h1;

    if (tid < 128) {
        float s = 0.0f;
        for (int i = 0; i < 16; i++) s += biassrc[i * 256 + mh * 128 + tid];
        sbias[tid] = s;
    }

    const int tx = tid & 15, oy = tid >> 4;   // oy 0..31, rows oy*4+rr
    const int c0 = tx * 4, c1 = 64 + tx * 4;

    ull acc[4][4];
    #pragma unroll
    for (int rr = 0; rr < 4; rr++)
        #pragma unroll
        for (int p = 0; p < 4; p++) acc[rr][p] = 0ULL;

    for (int ci = 0; ci < kchunks; ci++) {
        __syncthreads();
        const float* Ab = A + (size_t)(mh * 128) * as_r + (size_t)ci * as_c;
        for (int n = tid * 4; n < 8192; n += 2048) {
            int r = n >> 6, kk = n & 63;
            *(float4*)&wA[n] = *(const float4*)&Ab[(size_t)r * as_r + kk];
        }
        const float* Bb = Bsrc + (long)b * bs_b + (long)ci * bs_c + t0;
        for (int n = tid * 4; n < 8192; n += 2048) {
            int kk = n >> 7, tt = n & 127;
            *(float4*)&sB[n] = *(const float4*)&Bb[(size_t)kk * TN + tt];
        }
        __syncthreads();

        #pragma unroll 2
        for (int k = 0; k < 64; k++) {
            const float* br = sB + k * TT;
            ulonglong2 v0 = *(const ulonglong2*)&br[c0];
            ulonglong2 v1 = *(const ulonglong2*)&br[c1];
            ull bv[4] = { v0.x, v0.y, v1.x, v1.y };
            #pragma unroll
            for (int rr = 0; rr < 4; rr++) {
                ull a = bcast2(wA[(oy * 4 + rr) * 64 + k]);
                #pragma unroll
                for (int p = 0; p < 4; p++) ffma2(acc[rr][p], a, bv[p]);
            }
        }
    }

    #pragma unroll
    for (int rr = 0; rr < 4; rr++) {
        int row = oy * 4 + rr;
        float bias = sbias[row];
        float v[8];
        #pragma unroll
        for (int p = 0; p < 4; p++) {
            float2 f = up2(acc[rr][p]);
            v[2 * p]     = fmaxf(f.x + bias, 0.0f);
            v[2 * p + 1] = fmaxf(f.y + bias, 0.0f);
        }
        size_t rbase = (size_t)(b * 256 + mh * 128 + row) * TN;
        *(float4*)&D[rbase + t0 + c0] = make_float4(v[0], v[1], v[2], v[3]);
        *(float4*)&D[rbase + t0 + c1] = make_float4(v[4], v[5], v[6], v[7]);
    }
}

// ===========================================================================
// Kernel 5: FUSED HEAD  out = shift( end_w @ relu(out_w @ h1) ).
//   One CTA per (t-tile, b). h2 (256x128) lives entirely in smem.
//   512 thr: tx=tid&15 -> 8 t (c0,c1 chunks), oy=tid>>4 -> 8 rows (all 256).
// ===========================================================================
#define H_H2 0                 // h2 [256][128]
#define H_WA 32768             // A chunk [256][64]
#define H_SB 49152             // B chunk [64][128]
#define HEAD_SMEM_FLOATS (32768 + 16384 + 8192)
__global__ __launch_bounds__(512, 1)
void k_head(const float* __restrict__ out_w,
            const float* __restrict__ end_w,
            float* __restrict__ out)
{
    extern __shared__ float sm[];
    float* h2 = sm + H_H2;
    float* wA = sm + H_WA;
    float* sB = sm + H_SB;

    const int tid = threadIdx.x;
    const int t0  = blockIdx.x * TT;
    const int b   = blockIdx.y;

    const int tx = tid & 15, oy = tid >> 4;   // oy 0..31 -> rows oy*8..+7
    const int c0 = tx * 4, c1 = 64 + tx * 4;
    const int ro = oy * 8;

    // ---------------- Phase 1: h2 = relu(out_w @ h1_tile) ----------------
    ull acc[8][4];
    #pragma unroll
    for (int rr = 0; rr < 8; rr++)
        #pragma unroll
        for (int p = 0; p < 4; p++) acc[rr][p] = 0ULL;

    for (int ci = 0; ci < 4; ci++) {
        __syncthreads();
        // A chunk: out_w[256 rows][k = ci*64 .. +64)
        for (int n = tid * 4; n < 16384; n += 2048) {
            int r = n >> 6, kk = n & 63;
            *(float4*)&wA[n] = *(const float4*)&out_w[(size_t)r * 256 + ci * 64 + kk];
        }
        // B chunk: h1[(b*256 + ci*64 + kk)][t0 + tt]
        const float* Bb = g_h1 + ((size_t)b * 256 + ci * 64) * TN + t0;
        for (int n = tid * 4; n < 8192; n += 2048) {
            int kk = n >> 7, tt = n & 127;
            *(float4*)&sB[n] = *(const float4*)&Bb[(size_t)kk * TN + tt];
        }
        __syncthreads();

        #pragma unroll 2
        for (int k = 0; k < 64; k++) {
            const float* br = sB + k * TT;
            ulonglong2 v0 = *(const ulonglong2*)&br[c0];
            ulonglong2 v1 = *(const ulonglong2*)&br[c1];
            ull bv[4] = { v0.x, v0.y, v1.x, v1.y };
            #pragma unroll
            for (int rr = 0; rr < 8; rr++) {
                ull a = bcast2(wA[(ro + rr) * 64 + k]);
                #pragma unroll
                for (int p = 0; p < 4; p++) ffma2(acc[rr][p], a, bv[p]);
            }
        }
    }
    __syncthreads();   // before writing h2 region (wA/sB reused below)

    #pragma unroll
    for (int rr = 0; rr < 8; rr++) {
        int row = ro + rr;
        float2 f0 = up2(acc[rr][0]), f1 = up2(acc[rr][1]);
        float2 f2 = up2(acc[rr][2]), f3 = up2(acc[rr][3]);
        *(float4*)&h2[row * TT + c0] = make_float4(
            fmaxf(f0.x, 0.0f), fmaxf(f0.y, 0.0f), fmaxf(f1.x, 0.0f), fmaxf(f1.y, 0.0f));
        *(float4*)&h2[row * TT + c1] = make_float4(
            fmaxf(f2.x, 0.0f), fmaxf(f2.y, 0.0f), fmaxf(f3.x, 0.0f), fmaxf(f3.y, 0.0f));
    }
    __syncthreads();

    // ---------------- Phase 2: out = shift(end_w @ h2) ----------------
    #pragma unroll
    for (int rr = 0; rr < 8; rr++)
        #pragma unroll
        for (int p = 0; p < 4; p++) acc[rr][p] = 0ULL;

    for (int ci = 0; ci < 4; ci++) {
        __syncthreads();
        for (int n = tid * 4; n < 16384; n += 2048) {
            int r = n >> 6, kk = n & 63;
            *(float4*)&wA[n] = *(const float4*)&end_w[(size_t)r * 256 + ci * 64 + kk];
        }
        __syncthreads();

        #pragma unroll 2
        for (int k = 0; k < 64; k++) {
            const float* br = h2 + (ci * 64 + k) * TT;
            ulonglong2 v0 = *(const ulonglong2*)&br[c0];
            ulonglong2 v1 = *(const ulonglong2*)&br[c1];
            ull bv[4] = { v0.x, v0.y, v1.x, v1.y };
            #pragma unroll
            for (int rr = 0; rr < 8; rr++) {
                ull a = bcast2(wA[(ro + rr) * 64 + k]);
                #pragma unroll
                for (int p = 0; p < 4; p++) ffma2(acc[rr][p], a, bv[p]);
            }
        }
    }

    #pragma unroll
    for (int rr = 0; rr < 8; rr++) {
        int row = ro + rr;
        float v[8];
        #pragma unroll
        for (int p = 0; p < 4; p++) {
            float2 f = up2(acc[rr][p]);
            v[2 * p]     = f.x;
            v[2 * p + 1] = f.y;
        }
        size_t rbase = (size_t)(b * 256 + row) * TN;
        #pragma unroll
        for (int j = 0; j < 8; j++) {
            int t = t0 + ((j < 4) ? c0 + j : c1 + j - 4);
            if (t + 1 < TN) out[rbase + t + 1] = v[j];
            if (t == 0)     out[rbase] = 0.0f;
        }
    }
}

// ===========================================================================
// launcher
// ===========================================================================
extern "C" void kernel_launch(void* const* d_in, const int* in_sizes, int n_in,
                              void* d_out, int out_size)
{
    const float* features = (const float*)d_in[0];
    const int*   fwd      = (const int*)  d_in[1];
    const float* emb      = (const float*)d_in[2];
    const float* up_w     = (const float*)d_in[3];
    const float* up_b     = (const float*)d_in[4];
    const float* cond_w   = (const float*)d_in[5];
    const float* cond_b   = (const float*)d_in[6];
    const float* dil_w    = (const float*)d_in[7];
    const float* dil_b    = (const float*)d_in[8];
    const float* res_w    = (const float*)d_in[9];
    const float* res_b    = (const float*)d_in[10];
    const float* skip_w   = (const float*)d_in[11];
    const float* skip_b   = (const float*)d_in[12];
    const float* out_w    = (const float*)d_in[13];
    const float* end_w    = (const float*)d_in[14];
    float* out = (float*)d_out;

    cudaFuncSetAttribute(k_upsample, cudaFuncAttributeMaxDynamicSharedMemorySize,
                         UPS_SMEM_FLOATS * 4);
    cudaFuncSetAttribute(k_layer, cudaFuncAttributeMaxDynamicSharedMemorySize,
                         LAYER_SMEM_FLOATS * 4);
    cudaFuncSetAttribute(k_gemm, cudaFuncAttributeMaxDynamicSharedMemorySize,
                         GEMM_SMEM_FLOATS * 4);
    cudaFuncSetAttribute(k_head, cudaFuncAttributeMaxDynamicSharedMemorySize,
                         HEAD_SMEM_FLOATS * 4);

    k_upsample<<<200, 640, UPS_SMEM_FLOATS * 4>>>(features, up_w, up_b);
    k_embed<<<dim3((TN + 255) / 256, BN), 256>>>(fwd, emb);

    for (int i = 0; i < NLN; i++) {
        k_layer<<<PGRID, 512, LAYER_SMEM_FLOATS * 4>>>(
            dil_w, dil_b, cond_w, cond_b, res_w, res_b, i);
    }

    // skip-sum GEMM: h1 = relu(SW[256x1024] @ ACTS + sum_i skip_b)
    k_gemm<<<dim3(TN / TT, 2, BN), 512, GEMM_SMEM_FLOATS * 4>>>(
        skip_w, skip_b,
        /*kchunks=*/16, /*as_r=*/64, /*as_c=*/16384,
        /*bs_b=*/(long)64 * TN, /*bs_c=*/(long)4 * 64 * TN);

    // fused head: out = shift( end_w @ relu(out_w @ h1) )
    k_head<<<dim3(TN / TT, BN), 512, HEAD_SMEM_FLOATS * 4>>>(out_w, end_w, out);
}

// round 17
// speedup vs baseline: 1.8571x; 1.0304x over previous
#include <cuda_runtime.h>
#include <cuda_bf16.h>
#include <math.h>

// ---------------- problem constants ----------------
#define BN   4
#define TN   16000
#define NCN  80
#define NRN  64
#define NLN  16
#define TT   128     // t-tile for layer + gemm kernels
#define NUNITS 500   // 125 t-tiles * 4 batches
#define PGRID  148   // persistent grid for k_layer

// ---------------- device scratch (static, no dynamic alloc) ----------------
__device__ float g_cond[BN * NCN * TN];            //  [b][c][t]   20.5 MB
__device__ float g_x0  [BN * NRN * TN];            //  [b][k][t]   16.4 MB
__device__ float g_x1  [BN * NRN * TN];
__device__ float g_acts[NLN * BN * NRN * TN];      //  [i][b][k][t] 262 MB
__device__ float g_h1  [BN * 256 * TN];            //  [b][o][t]   65.5 MB

typedef unsigned long long ull;

// ---------------- packed f32x2 helpers (sm_103a FFMA2) ----------------
__device__ __forceinline__ void ffma2(ull& d, ull a, ull b) {
    asm("fma.rn.f32x2 %0, %1, %2, %0;" : "+l"(d) : "l"(a), "l"(b));
}
__device__ __forceinline__ ull pk2(float x, float y) {
    ull r; asm("mov.b64 %0, {%1, %2};" : "=l"(r) : "f"(x), "f"(y)); return r;
}
__device__ __forceinline__ ull bcast2(float x) {
    ull r; asm("mov.b64 %0, {%1, %1};" : "=l"(r) : "f"(x)); return r;
}
__device__ __forceinline__ float2 up2(ull v) {
    float2 f; asm("mov.b64 {%0, %1}, %2;" : "=f"(f.x), "=f"(f.y) : "l"(v)); return f;
}

// ---------------- fast activations ----------------
__device__ __forceinline__ float fast_sigmoid(float x) {
    return __fdividef(1.0f, 1.0f + __expf(-x));
}
__device__ __forceinline__ float fast_tanh(float x) {
    float ax = fabsf(x);
    float e  = __expf(-2.0f * ax);
    float t  = __fdividef(1.0f - e, 1.0f + e);
    return copysignf(t, x);
}

// ---------------- mma.sync helpers (base ISA, works on sm_103) ----------------
__device__ __forceinline__ void mma16816(float* c, const unsigned* a, const unsigned* b) {
    asm volatile(
        "mma.sync.aligned.m16n8k16.row.col.f32.bf16.bf16.f32 "
        "{%0,%1,%2,%3}, {%4,%5,%6,%7}, {%8,%9}, {%0,%1,%2,%3};"
        : "+f"(c[0]), "+f"(c[1]), "+f"(c[2]), "+f"(c[3])
        : "r"(a[0]), "r"(a[1]), "r"(a[2]), "r"(a[3]), "r"(b[0]), "r"(b[1]));
}
__device__ __forceinline__ void f2bf_split(float v, unsigned short& h, unsigned short& l) {
    __nv_bfloat16 hb = __float2bfloat16(v);
    float hf = __bfloat162float(hb);
    __nv_bfloat16 lb = __float2bfloat16(v - hf);
    h = __bfloat16_as_ushort(hb);
    l = __bfloat16_as_ushort(lb);
}

// ===========================================================================
// Kernel 1: transposed-conv upsampler by output phase (640 thr, FFMA2).
// ===========================================================================
#define UPS_SMEM_FLOATS (25600 + 25600)
__global__ __launch_bounds__(640, 1)
void k_upsample(const float* __restrict__ features,
                const float* __restrict__ up_w,
                const float* __restrict__ up_b)
{
    extern __shared__ float sm[];
    float* ws = sm;            // [j][i][o] : 4*80*80
    float* fs = sm + 25600;    // [b][i][s] : 4*80*80

    const int r   = blockIdx.x;
    const int tid = threadIdx.x;

    for (int n = tid; n < 25600; n += 640) fs[n] = features[n];
    for (int n = tid; n < 25600; n += 640) {
        int j = n / 6400, rem = n % 6400, i = rem / 80, o = rem % 80;
        ws[n] = up_w[(i * 80 + o) * 800 + 200 * j + r];
    }
    __syncthreads();

    const int b  = tid / 160;
    const int oh = (tid % 160) / 80;
    const int q  = tid % 80;
    const int t  = 200 * q + r;

    ull acc[20];
    #pragma unroll
    for (int o2 = 0; o2 < 20; o2++)
        acc[o2] = pk2(__ldg(&up_b[oh * 40 + 2 * o2]), __ldg(&up_b[oh * 40 + 2 * o2 + 1]));

    #pragma unroll
    for (int j = 0; j < 4; j++) {
        int s = q - j;
        if (s >= 0) {
            const float* fsb = fs + b * 6400 + s;
            const float* wsj = ws + j * 6400 + oh * 40;
            #pragma unroll 2
            for (int i = 0; i < 80; i++) {
                ull f = bcast2(fsb[i * 80]);
                const ull* w = (const ull*)(wsj + i * 80);
                #pragma unroll
                for (int o2 = 0; o2 < 20; o2++) ffma2(acc[o2], w[o2], f);
            }
        }
    }
    float* outp = g_cond + (size_t)(b * 80 + oh * 40) * TN + t;
    #pragma unroll
    for (int o2 = 0; o2 < 20; o2++) {
        float2 v = up2(acc[o2]);
        outp[(size_t)(2 * o2) * TN]     = v.x;
        outp[(size_t)(2 * o2 + 1) * TN] = v.y;
    }
}

// ===========================================================================
// Kernel 2: embedding gather  x0[b][k][t] = emb[fi[b][t]][k]
// ===========================================================================
__global__ void k_embed(const int* __restrict__ fi,
                        const float* __restrict__ emb)
{
    int b = blockIdx.y;
    int t = blockIdx.x * 256 + threadIdx.x;
    if (t >= TN) return;
    int idx = fi[b * TN + t];
    const float* row = emb + idx * 64;
    float* out = g_x0 + (size_t)(b * 64) * TN + t;
    #pragma unroll
    for (int k = 0; k < 64; k++) out[(size_t)k * TN] = __ldg(row + k);
}

// ===========================================================================
// Kernel 3: gated WaveNet layer — PERSISTENT (148 CTAs x 512 thr).
//   (R11-proven version, unchanged.)
// ===========================================================================
#define L_DW0   0              // dw0T [k][128]
#define L_DW1   8192           // dw1T [k][128]
#define L_CW    16384          // cwT  [c][128]
#define L_RW    26624          // rwT  [k][64]
#define L_GB    30720
#define L_RB    30848
#define L_XE    30912          // [64][256]
#define L_SC    47296          // [80][128]  (reused as acts tile [64][128])
#define LAYER_SMEM_FLOATS 57536

__global__ __launch_bounds__(512, 1)
void k_layer(const float* __restrict__ dil_w, const float* __restrict__ dil_b,
             const float* __restrict__ cond_w, const float* __restrict__ cond_b,
             const float* __restrict__ res_w,  const float* __restrict__ res_b,
             int li)
{
    extern __shared__ float sm[];
    float* dw0 = sm + L_DW0;
    float* dw1 = sm + L_DW1;
    float* cw  = sm + L_CW;
    float* rw  = sm + L_RW;
    float* gb  = sm + L_GB;
    float* rb  = sm + L_RB;
    float* xe  = sm + L_XE;
    float* sc  = sm + L_SC;
    float* sa  = sm + L_SC;     // overlapped, separated by barriers

    const int tid = threadIdx.x;
    const int d   = 1 << (li & 7);
    const int has_res = (li < NLN - 1);

    const float* xin  = (li & 1) ? g_x1 : g_x0;
    float*       xout = (li & 1) ? g_x0 : g_x1;
    float*       actsbase = g_acts + (size_t)li * BN * NRN * TN;

    const float* dwb = dil_w + (size_t)li * 16384;
    const float* dbb = dil_b + li * 128;
    const float* cwb = cond_w + (size_t)li * 128 * 80;
    const float* cbb = cond_b + li * 128;

    // ---- one-time weight staging (transposed into smem) ----
    for (int n = tid; n < 8192; n += 512) {
        int k = n >> 7, row = n & 127;
        float2 v = ((const float2*)dwb)[row * 64 + k];
        dw0[n] = v.x; dw1[n] = v.y;          // n = k*128 + row
    }
    for (int n = tid; n < 10240; n += 512) {
        int c = n >> 7, row = n & 127;
        cw[n] = cwb[row * 80 + c];           // n = c*128 + row
    }
    if (has_res) {
        const float* rwb = res_w + (size_t)li * 4096;
        for (int n = tid; n < 4096; n += 512) {
            int k = n >> 6, row = n & 63;
            rw[n] = rwb[row * 64 + k];       // n = k*64 + row
        }
        if (tid < 64) rb[tid] = res_b[li * 64 + tid];
    }
    if (tid < 128) gb[tid] = dbb[tid] + cbb[tid];

    const int tx = tid & 31, oy = tid >> 5;   // oy 0..15, warp-uniform
    const int c0 = tx * 4;
    const int ro = 4 * oy;

    // ---- persistent unit loop ----
    for (int u = blockIdx.x; u < NUNITS; u += PGRID) {
        const int b  = u & 3;
        const int t0 = (u >> 2) * TT;
        float* acts = actsbase;

        __syncthreads();   // protect sa (prev unit) before restaging sc/xe

        if (t0 == 0) {
            for (int n = tid; n < 64 * 256; n += 512) {
                int k = n >> 8, tt = n & 255;
                int gt = t0 - 128 + tt;
                xe[n] = (gt >= 0) ? xin[(size_t)(b * 64 + k) * TN + gt] : 0.0f;
            }
        } else {
            for (int n = tid * 4; n < 64 * 256; n += 2048) {
                int k = n >> 8, tt = n & 255;
                *(float4*)&xe[n] = *(const float4*)&xin[(size_t)(b * 64 + k) * TN + t0 - 128 + tt];
            }
        }
        for (int n = tid * 4; n < 80 * TT; n += 2048) {
            int c = n >> 7, tt = n & 127;
            *(float4*)&sc[n] = *(const float4*)&g_cond[(size_t)(b * 80 + c) * TN + t0 + tt];
        }
        __syncthreads();

        ull at[4][2], as_[4][2];
        #pragma unroll
        for (int rr = 0; rr < 4; rr++) {
            ull bt = bcast2(gb[ro + rr]);
            ull bs = bcast2(gb[64 + ro + rr]);
            at[rr][0] = bt; at[rr][1] = bt;
            as_[rr][0] = bs; as_[rr][1] = bs;
        }

        // ---- dilated-pair GEMM (K=64, two operands per k) ----
        const int dm4 = (d & 3) == 0;
        #pragma unroll 2
        for (int k = 0; k < 64; k++) {
            const float* xr = xe + k * 256;
            ull xc[2], xp[2];
            {
                ulonglong2 v0 = *(const ulonglong2*)&xr[128 + c0];
                xc[0] = v0.x; xc[1] = v0.y;
            }
            if (dm4) {
                ulonglong2 v0 = *(const ulonglong2*)&xr[128 - d + c0];
                xp[0] = v0.x; xp[1] = v0.y;
            } else if (d == 2) {
                xp[0] = *(const ull*)&xr[126 + c0];
                xp[1] = *(const ull*)&xr[128 + c0];
            } else { // d == 1
                xp[0] = pk2(xr[127 + c0], xr[128 + c0]);
                xp[1] = pk2(xr[129 + c0], xr[130 + c0]);
            }
            float4 w0t = *(const float4*)&dw0[k * 128 + ro];
            float4 w0s = *(const float4*)&dw0[k * 128 + 64 + ro];
            float4 w1t = *(const float4*)&dw1[k * 128 + ro];
            float4 w1s = *(const float4*)&dw1[k * 128 + 64 + ro];
            const float* w0tp = (const float*)&w0t;
            const float* w0sp = (const float*)&w0s;
            const float* w1tp = (const float*)&w1t;
            const float* w1sp = (const float*)&w1s;
            #pragma unroll
            for (int rr = 0; rr < 4; rr++) {
                ull b0t = bcast2(w0tp[rr]), b1t = bcast2(w1tp[rr]);
                ull b0s = bcast2(w0sp[rr]), b1s = bcast2(w1sp[rr]);
                #pragma unroll
                for (int p = 0; p < 2; p++) {
                    ffma2(at[rr][p],  b0t, xp[p]);  ffma2(at[rr][p],  b1t, xc[p]);
                    ffma2(as_[rr][p], b0s, xp[p]);  ffma2(as_[rr][p], b1s, xc[p]);
                }
            }
        }

        // ---- cond GEMM (K=80) ----
        #pragma unroll 2
        for (int c = 0; c < 80; c++) {
            const float* scr = sc + c * TT;
            ulonglong2 v0 = *(const ulonglong2*)&scr[c0];
            ull xc[2] = { v0.x, v0.y };
            float4 wt4 = *(const float4*)&cw[c * 128 + ro];
            float4 wg4 = *(const float4*)&cw[c * 128 + 64 + ro];
            const float* wtp = (const float*)&wt4;
            const float* wgp = (const float*)&wg4;
            #pragma unroll
            for (int rr = 0; rr < 4; rr++) {
                ull wt = bcast2(wtp[rr]);
                ull wg = bcast2(wgp[rr]);
                #pragma unroll
                for (int p = 0; p < 2; p++) {
                    ffma2(at[rr][p], wt, xc[p]);
                    ffma2(as_[rr][p], wg, xc[p]);
                }
            }
        }

        // ---- gating ----
        float av[4][4];
        #pragma unroll
        for (int rr = 0; rr < 4; rr++)
            #pragma unroll
            for (int p = 0; p < 2; p++) {
                float2 t2 = up2(at[rr][p]);
                float2 s2 = up2(as_[rr][p]);
                av[rr][2 * p]     = fast_tanh(t2.x) * fast_sigmoid(s2.x);
                av[rr][2 * p + 1] = fast_tanh(t2.y) * fast_sigmoid(s2.y);
            }

        __syncthreads();   // done reading sc; region becomes sa

        #pragma unroll
        for (int rr = 0; rr < 4; rr++) {
            int row = ro + rr;
            float4 q0 = make_float4(av[rr][0], av[rr][1], av[rr][2], av[rr][3]);
            *(float4*)&sa[row * TT + c0] = q0;
            *(float4*)&(acts + (size_t)(b * 64 + row) * TN + t0)[c0] = q0;
        }
        if (!has_res) continue;
        __syncthreads();

        // ---- residual GEMM (K=64) + x add ----
        ull rc[4][2];
        #pragma unroll
        for (int rr = 0; rr < 4; rr++) {
            ull bv = bcast2(rb[ro + rr]);
            rc[rr][0] = bv; rc[rr][1] = bv;
        }
        #pragma unroll 2
        for (int k = 0; k < 64; k++) {
            const float* ar = sa + k * TT;
            ulonglong2 v0 = *(const ulonglong2*)&ar[c0];
            float4 wr4 = *(const float4*)&rw[k * 64 + ro];
            const float* wrp = (const float*)&wr4;
            #pragma unroll
            for (int rr = 0; rr < 4; rr++) {
                ull w = bcast2(wrp[rr]);
                ffma2(rc[rr][0], w, v0.x);
                ffma2(rc[rr][1], w, v0.y);
            }
        }
        #pragma unroll
        for (int rr = 0; rr < 4; rr++) {
            int row = ro + rr;
            float4 xv = *(const float4*)&xe[row * 256 + 128 + c0];
            float2 r0 = up2(rc[rr][0]), r1 = up2(rc[rr][1]);
            float4 o;
            o.x = r0.x + xv.x;  o.y = r0.y + xv.y;
            o.z = r1.x + xv.z;  o.w = r1.y + xv.w;
            *(float4*)&(xout + (size_t)(b * 64 + row) * TN + t0)[c0] = o;
        }
    }
}

// ===========================================================================
// Kernel 4: skip-sum GEMM on mma.sync bf16 (hi/lo split).
//   D[128 rows][128 t] per CTA; K = 16 layer-chunks of 64.
//   16 warps: warp (wm = w&3, wn = w>>2) owns rows [wm*32,+32) x t [wn*32,+32)
//   = 2 m-atoms x 4 n-atoms of m16n8k16. 3 MMAs per atom per k16 step:
//   Whi*Ahi + Whi*Alo + Wlo*Ahi.  h1 = relu(D + bias).
// ===========================================================================
#define SK_STR 66              // ushort stride (132 B) to stagger banks
#define SK_AHI 512
#define SK_ALO (512 + 16896)
#define SK_BHI (512 + 2 * 16896)
#define SK_BLO (512 + 3 * 16896)
#define SKIP_SMEM_BYTES (512 + 4 * 16896)   // 68096

__global__ __launch_bounds__(512, 1)
void k_skip(const float* __restrict__ skip_w,
            const float* __restrict__ skip_b)
{
    extern __shared__ char smc[];
    float* sbias = (float*)smc;
    unsigned short* Ahi = (unsigned short*)(smc + SK_AHI);
    unsigned short* Alo = (unsigned short*)(smc + SK_ALO);
    unsigned short* Bhi = (unsigned short*)(smc + SK_BHI);
    unsigned short* Blo = (unsigned short*)(smc + SK_BLO);

    const int tid = threadIdx.x;
    const int t0  = blockIdx.x * TT;
    const int mh  = blockIdx.y;
    const int b   = blockIdx.z;

    const int w   = tid >> 5, lane = tid & 31;
    const int wm  = w & 3, wn = w >> 2;
    const int gid = lane >> 2, tig = lane & 3;

    if (tid < 128) {
        float s = 0.0f;
        for (int i = 0; i < 16; i++) s += skip_b[i * 256 + mh * 128 + tid];
        sbias[tid] = s;
    }

    float acc[2][4][4];
    #pragma unroll
    for (int mi = 0; mi < 2; mi++)
        #pragma unroll
        for (int ni = 0; ni < 4; ni++)
            #pragma unroll
            for (int j = 0; j < 4; j++) acc[mi][ni][j] = 0.0f;

    for (int kc = 0; kc < 16; kc++) {
        __syncthreads();
        // stage A: skip_w chunk [128 rows][64 k] fp32 -> bf16 hi/lo [row][k]
        const float* Ab = skip_w + ((size_t)kc * 256 + mh * 128) * 64;
        for (int n = tid; n < 8192; n += 512) {
            int r = n >> 6, k = n & 63;
            unsigned short h, l;
            f2bf_split(Ab[n], h, l);
            Ahi[r * SK_STR + k] = h;
            Alo[r * SK_STR + k] = l;
        }
        // stage B: acts chunk [64 k][128 t] fp32 -> bf16 hi/lo TRANSPOSED [t][k]
        const float* Bb = g_acts + ((size_t)kc * BN + b) * (size_t)NRN * TN + t0;
        for (int n = tid; n < 8192; n += 512) {
            int k = n >> 7, t = n & 127;
            unsigned short h, l;
            f2bf_split(Bb[(size_t)k * TN + t], h, l);
            Bhi[t * SK_STR + k] = h;
            Blo[t * SK_STR + k] = l;
        }
        __syncthreads();

        #pragma unroll
        for (int ks = 0; ks < 4; ks++) {
            const int kb = ks * 16;
            unsigned ah[2][4], al[2][4];
            #pragma unroll
            for (int mi = 0; mi < 2; mi++) {
                int r0 = wm * 32 + mi * 16 + gid;
                int cb = kb + tig * 2;
                ah[mi][0] = *(const unsigned*)&Ahi[r0 * SK_STR + cb];
                ah[mi][1] = *(const unsigned*)&Ahi[(r0 + 8) * SK_STR + cb];
                ah[mi][2] = *(const unsigned*)&Ahi[r0 * SK_STR + cb + 8];
                ah[mi][3] = *(const unsigned*)&Ahi[(r0 + 8) * SK_STR + cb + 8];
                al[mi][0] = *(const unsigned*)&Alo[r0 * SK_STR + cb];
                al[mi][1] = *(const unsigned*)&Alo[(r0 + 8) * SK_STR + cb];
                al[mi][2] = *(const unsigned*)&Alo[r0 * SK_STR + cb + 8];
                al[mi][3] = *(const unsigned*)&Alo[(r0 + 8) * SK_STR + cb + 8];
            }
            #pragma unroll
            for (int ni = 0; ni < 4; ni++) {
                int tcol = wn * 32 + ni * 8 + gid;
                int cb = kb + tig * 2;
                unsigned bh[2], bl[2];
                bh[0] = *(const unsigned*)&Bhi[tcol * SK_STR + cb];
                bh[1] = *(const unsigned*)&Bhi[tcol * SK_STR + cb + 8];
                bl[0] = *(const unsigned*)&Blo[tcol * SK_STR + cb];
                bl[1] = *(const unsigned*)&Blo[tcol * SK_STR + cb + 8];
                #pragma unroll
                for (int mi = 0; mi < 2; mi++) {
                    mma16816(acc[mi][ni], ah[mi], bh);
                    mma16816(acc[mi][ni], ah[mi], bl);
                    mma16816(acc[mi][ni], al[mi], bh);
                }
            }
        }
    }

    // ---- epilogue: bias + relu, direct stores ----
    #pragma unroll
    for (int mi = 0; mi < 2; mi++) {
        int r0 = wm * 32 + mi * 16 + gid;
        int gr0 = b * 256 + mh * 128 + r0;
        float b0 = sbias[r0], b1 = sbias[r0 + 8];
        #pragma unroll
        for (int ni = 0; ni < 4; ni++) {
            int t = t0 + wn * 32 + ni * 8 + tig * 2;
            float2 v0, v1;
            v0.x = fmaxf(acc[mi][ni][0] + b0, 0.0f);
            v0.y = fmaxf(acc[mi][ni][1] + b0, 0.0f);
            v1.x = fmaxf(acc[mi][ni][2] + b1, 0.0f);
            v1.y = fmaxf(acc[mi][ni][3] + b1, 0.0f);
            *(float2*)&g_h1[(size_t)gr0 * TN + t]       = v0;
            *(float2*)&g_h1[(size_t)(gr0 + 8) * TN + t] = v1;
        }
    }
}

// ===========================================================================
// Kernel 5: FUSED HEAD  out = shift( end_w @ relu(out_w @ h1) ).
//   (R13-proven version, unchanged.)
// ===========================================================================
#define H_H2 0                 // h2 [256][128]
#define H_WA 32768             // A chunk [256][64]
#define H_SB 49152             // B chunk [64][128]
#define HEAD_SMEM_FLOATS (32768 + 16384 + 8192)
__global__ __launch_bounds__(512, 1)
void k_head(const float* __restrict__ out_w,
            const float* __restrict__ end_w,
            float* __restrict__ out)
{
    extern __shared__ float sm[];
    float* h2 = sm + H_H2;
    float* wA = sm + H_WA;
    float* sB = sm + H_SB;

    const int tid = threadIdx.x;
    const int t0  = blockIdx.x * TT;
    const int b   = blockIdx.y;

    const int tx = tid & 15, oy = tid >> 4;   // oy 0..31 -> rows oy*8..+7
    const int c0 = tx * 4, c1 = 64 + tx * 4;
    const int ro = oy * 8;

    // ---------------- Phase 1: h2 = relu(out_w @ h1_tile) ----------------
    ull acc[8][4];
    #pragma unroll
    for (int rr = 0; rr < 8; rr++)
        #pragma unroll
        for (int p = 0; p < 4; p++) acc[rr][p] = 0ULL;

    for (int ci = 0; ci < 4; ci++) {
        __syncthreads();
        for (int n = tid * 4; n < 16384; n += 2048) {
            int r = n >> 6, kk = n & 63;
            *(float4*)&wA[n] = *(const float4*)&out_w[(size_t)r * 256 + ci * 64 + kk];
        }
        const float* Bb = g_h1 + ((size_t)b * 256 + ci * 64) * TN + t0;
        for (int n = tid * 4; n < 8192; n += 2048) {
            int kk = n >> 7, tt = n & 127;
            *(float4*)&sB[n] = *(const float4*)&Bb[(size_t)kk * TN + tt];
        }
        __syncthreads();

        #pragma unroll 2
        for (int k = 0; k < 64; k++) {
            const float* br = sB + k * TT;
            ulonglong2 v0 = *(const ulonglong2*)&br[c0];
            ulonglong2 v1 = *(const ulonglong2*)&br[c1];
            ull bv[4] = { v0.x, v0.y, v1.x, v1.y };
            #pragma unroll
            for (int rr = 0; rr < 8; rr++) {
                ull a = bcast2(wA[(ro + rr) * 64 + k]);
                #pragma unroll
                for (int p = 0; p < 4; p++) ffma2(acc[rr][p], a, bv[p]);
            }
        }
    }
    __syncthreads();   // before writing h2 region (wA/sB reused below)

    #pragma unroll
    for (int rr = 0; rr < 8; rr++) {
        int row = ro + rr;
        float2 f0 = up2(acc[rr][0]), f1 = up2(acc[rr][1]);
        float2 f2 = up2(acc[rr][2]), f3 = up2(acc[rr][3]);
        *(float4*)&h2[row * TT + c0] = make_float4(
            fmaxf(f0.x, 0.0f), fmaxf(f0.y, 0.0f), fmaxf(f1.x, 0.0f), fmaxf(f1.y, 0.0f));
        *(float4*)&h2[row * TT + c1] = make_float4(
            fmaxf(f2.x, 0.0f), fmaxf(f2.y, 0.0f), fmaxf(f3.x, 0.0f), fmaxf(f3.y, 0.0f));
    }
    __syncthreads();

    // ---------------- Phase 2: out = shift(end_w @ h2) ----------------
    #pragma unroll
    for (int rr = 0; rr < 8; rr++)
        #pragma unroll
        for (int p = 0; p < 4; p++) acc[rr][p] = 0ULL;

    for (int ci = 0; ci < 4; ci++) {
        __syncthreads();
        for (int n = tid * 4; n < 16384; n += 2048) {
            int r = n >> 6, kk = n & 63;
            *(float4*)&wA[n] = *(const float4*)&end_w[(size_t)r * 256 + ci * 64 + kk];
        }
        __syncthreads();

        #pragma unroll 2
        for (int k = 0; k < 64; k++) {
            const float* br = h2 + (ci * 64 + k) * TT;
            ulonglong2 v0 = *(const ulonglong2*)&br[c0];
            ulonglong2 v1 = *(const ulonglong2*)&br[c1];
            ull bv[4] = { v0.x, v0.y, v1.x, v1.y };
            #pragma unroll
            for (int rr = 0; rr < 8; rr++) {
                ull a = bcast2(wA[(ro + rr) * 64 + k]);
                #pragma unroll
                for (int p = 0; p < 4; p++) ffma2(acc[rr][p], a, bv[p]);
            }
        }
    }

    #pragma unroll
    for (int rr = 0; rr < 8; rr++) {
        int row = ro + rr;
        float v[8];
        #pragma unroll
        for (int p = 0; p < 4; p++) {
            float2 f = up2(acc[rr][p]);
            v[2 * p]     = f.x;
            v[2 * p + 1] = f.y;
        }
        size_t rbase = (size_t)(b * 256 + row) * TN;
        #pragma unroll
        for (int j = 0; j < 8; j++) {
            int t = t0 + ((j < 4) ? c0 + j : c1 + j - 4);
            if (t + 1 < TN) out[rbase + t + 1] = v[j];
            if (t == 0)     out[rbase] = 0.0f;
        }
    }
}

// ===========================================================================
// launcher
// ===========================================================================
extern "C" void kernel_launch(void* const* d_in, const int* in_sizes, int n_in,
                              void* d_out, int out_size)
{
    const float* features = (const float*)d_in[0];
    const int*   fwd      = (const int*)  d_in[1];
    const float* emb      = (const float*)d_in[2];
    const float* up_w     = (const float*)d_in[3];
    const float* up_b     = (const float*)d_in[4];
    const float* cond_w   = (const float*)d_in[5];
    const float* cond_b   = (const float*)d_in[6];
    const float* dil_w    = (const float*)d_in[7];
    const float* dil_b    = (const float*)d_in[8];
    const float* res_w    = (const float*)d_in[9];
    const float* res_b    = (const float*)d_in[10];
    const float* skip_w   = (const float*)d_in[11];
    const float* skip_b   = (const float*)d_in[12];
    const float* out_w    = (const float*)d_in[13];
    const float* end_w    = (const float*)d_in[14];
    float* out = (float*)d_out;

    cudaFuncSetAttribute(k_upsample, cudaFuncAttributeMaxDynamicSharedMemorySize,
                         UPS_SMEM_FLOATS * 4);
    cudaFuncSetAttribute(k_layer, cudaFuncAttributeMaxDynamicSharedMemorySize,
                         LAYER_SMEM_FLOATS * 4);
    cudaFuncSetAttribute(k_skip, cudaFuncAttributeMaxDynamicSharedMemorySize,
                         SKIP_SMEM_BYTES);
    cudaFuncSetAttribute(k_head, cudaFuncAttributeMaxDynamicSharedMemorySize,
                         HEAD_SMEM_FLOATS * 4);

    k_upsample<<<200, 640, UPS_SMEM_FLOATS * 4>>>(features, up_w, up_b);
    k_embed<<<dim3((TN + 255) / 256, BN), 256>>>(fwd, emb);

    for (int i = 0; i < NLN; i++) {
        k_layer<<<PGRID, 512, LAYER_SMEM_FLOATS * 4>>>(
            dil_w, dil_b, cond_w, cond_b, res_w, res_b, i);
    }

    // skip-sum GEMM on mma.sync bf16: h1 = relu(SW @ ACTS + sum_i skip_b)
    k_skip<<<dim3(TN / TT, 2, BN), 512, SKIP_SMEM_BYTES>>>(skip_w, skip_b);

    // fused head: out = shift( end_w @ relu(out_w @ h1) )
    k_head<<<dim3(TN / TT, BN), 512, HEAD_SMEM_FLOATS * 4>>>(out_w, end_w, out);
}